// round 13
// baseline (speedup 1.0000x reference)
#include <cuda_runtime.h>
#include <cuda_bf16.h>
#include <math.h>
#include <stddef.h>

#define NN 50000
#define EE 800000
#define FF 64
#define EDD 16
#define GG 64
#define LL 2
#define SCB ((NN + 1023) / 1024)

typedef unsigned long long u64;
typedef unsigned int u32;

// ---------------- packed f32x2 helpers ----------------
__device__ __forceinline__ u64 pk2(float x, float y) {
    u64 r; asm("mov.b64 %0,{%1,%2};" : "=l"(r) : "f"(x), "f"(y)); return r;
}
__device__ __forceinline__ float2 up2(u64 v) {
    float2 r; asm("mov.b64 {%0,%1},%2;" : "=f"(r.x), "=f"(r.y) : "l"(v)); return r;
}
__device__ __forceinline__ u64 ffma2(u64 a, u64 b, u64 c) {
    u64 d; asm("fma.rn.f32x2 %0,%1,%2,%3;" : "=l"(d) : "l"(a), "l"(b), "l"(c)); return d;
}
__device__ __forceinline__ u64 fadd2(u64 a, u64 b) {
    u64 d; asm("add.rn.f32x2 %0,%1,%2;" : "=l"(d) : "l"(a), "l"(b)); return d;
}

// ---------------- bf16 / mma / cp.async helpers ----------------
__device__ __forceinline__ void mma16816(float* d, const u32* a, const u32* b) {
    asm volatile("mma.sync.aligned.m16n8k16.row.col.f32.bf16.bf16.f32 "
                 "{%0,%1,%2,%3},{%4,%5,%6,%7},{%8,%9},{%0,%1,%2,%3};"
                 : "+f"(d[0]), "+f"(d[1]), "+f"(d[2]), "+f"(d[3])
                 : "r"(a[0]), "r"(a[1]), "r"(a[2]), "r"(a[3]), "r"(b[0]), "r"(b[1]));
}
__device__ __forceinline__ void bfsplit2(float a, float b, u32& hi, u32& lo) {
    __nv_bfloat16 ah = __float2bfloat16_rn(a);
    __nv_bfloat16 bh = __float2bfloat16_rn(b);
    __nv_bfloat16 al = __float2bfloat16_rn(a - __bfloat162float(ah));
    __nv_bfloat16 bl = __float2bfloat16_rn(b - __bfloat162float(bh));
    unsigned short ahs = *reinterpret_cast<unsigned short*>(&ah);
    unsigned short bhs = *reinterpret_cast<unsigned short*>(&bh);
    unsigned short als = *reinterpret_cast<unsigned short*>(&al);
    unsigned short bls = *reinterpret_cast<unsigned short*>(&bl);
    hi = (u32)ahs | ((u32)bhs << 16);
    lo = (u32)als | ((u32)bls << 16);
}
__device__ __forceinline__ u32 s2u(const void* p) {
    return (u32)__cvta_generic_to_shared(p);
}
__device__ __forceinline__ void cpa16(u32 dst, const void* src, int sz) {
    asm volatile("cp.async.cg.shared.global [%0],[%1],16,%2;" :: "r"(dst), "l"(src), "r"(sz));
}
#define CP_COMMIT asm volatile("cp.async.commit_group;")
#define CP_WAIT1  asm volatile("cp.async.wait_group 1;")
#define CP_WAIT0  asm volatile("cp.async.wait_group 0;")

// ---------------- scratch ----------------
__device__ int   g_deg[NN];
__device__ int   g_rowptr[NN + 1];
__device__ int   g_cursor[NN];
__device__ int   g_bsum[64];
__device__ int   g_csr_src[EE];
__device__ float g_eaperm[(size_t)EE * EDD];
__device__ float g_amp[NN];
__device__ float g_att[NN];
__device__ float g_logsum;
__device__ float g_P[NN * FF];
__device__ float g_Q[NN * FF];
__device__ float g_Wc[EDD * FF];
__device__ float g_hb[FF];
__device__ float g_bias2[FF];
__device__ float g_C[(size_t)NN * 192];
__device__ float g_y[NN * FF];
__device__ float g_bnsum[FF];
__device__ float g_bnsq[FF];
__device__ float g_bnA[FF];
__device__ float g_bnB[FF];
__device__ float g_gsum[GG * FF];
__device__ int   g_gcnt[GG];
__device__ __nv_bfloat16 g_Ah[(size_t)NN * 320];
__device__ __nv_bfloat16 g_Al[(size_t)NN * 320];
__device__ __nv_bfloat16 g_Bth[192 * 320];
__device__ __nv_bfloat16 g_Btl[192 * 320];
__device__ __nv_bfloat16 g_Wth[128 * 64];
__device__ __nv_bfloat16 g_Wtl[128 * 64];

// ---------------- init / degree / CSR ----------------
__global__ void k_init() {
    int i  = blockIdx.x * blockDim.x + threadIdx.x;
    int nt = gridDim.x * blockDim.x;
    for (int j = i; j < NN; j += nt) { g_deg[j] = 0; g_cursor[j] = 0; }
    for (int j = i; j < GG * FF; j += nt) g_gsum[j] = 0.f;
    if (i < GG) g_gcnt[i] = 0;
    if (i == 0) g_logsum = 0.f;
}

__global__ void k_deg(const int* __restrict__ ei) {
    int e = blockIdx.x * blockDim.x + threadIdx.x;
    if (e < EE) atomicAdd(&g_deg[ei[EE + e]], 1);
}

__global__ void k_scan1() {
    int tid = threadIdx.x, lane = tid & 31, wid = tid >> 5;
    int i = blockIdx.x * 1024 + tid;
    int v = (i < NN) ? g_deg[i] : 0;
    float lv = (i < NN) ? logf((float)v + 1.0f) : 0.0f;
#pragma unroll
    for (int off = 16; off > 0; off >>= 1) lv += __shfl_xor_sync(0xffffffffu, lv, off);
    if (lane == 0) atomicAdd(&g_logsum, lv);
    int x = v;
#pragma unroll
    for (int off = 1; off < 32; off <<= 1) {
        int t = __shfl_up_sync(0xffffffffu, x, off);
        if (lane >= off) x += t;
    }
    __shared__ int ws[32];
    if (lane == 31) ws[wid] = x;
    __syncthreads();
    if (wid == 0) {
        int s = ws[lane];
#pragma unroll
        for (int off = 1; off < 32; off <<= 1) {
            int t = __shfl_up_sync(0xffffffffu, s, off);
            if (lane >= off) s += t;
        }
        ws[lane] = s;
    }
    __syncthreads();
    int wbase = wid ? ws[wid - 1] : 0;
    if (i < NN) g_rowptr[i] = wbase + x - v;
    if (tid == 1023) g_bsum[blockIdx.x] = wbase + x;
}

__global__ void k_scan3() {
    __shared__ int sb[64];
    __shared__ int s_off, s_tot;
    int t = threadIdx.x;
    if (t < 64) sb[t] = (t < SCB) ? g_bsum[t] : 0;
    __syncthreads();
    if (t == 0) {
        int off = 0, tot = 0;
        for (int j = 0; j < SCB; j++) {
            if (j < (int)blockIdx.x) off += sb[j];
            tot += sb[j];
        }
        s_off = off; s_tot = tot;
    }
    __syncthreads();
    int i = blockIdx.x * 1024 + t;
    if (i < NN) {
        g_rowptr[i] += s_off;
        float avg = g_logsum / (float)NN;
        float d = (float)g_deg[i];
        float logd = logf(fmaxf(d, 1.0f) + 1.0f);
        g_amp[i] = logd / avg;
        g_att[i] = avg / logd;
    }
    if (blockIdx.x == gridDim.x - 1 && t == 0) g_rowptr[NN] = s_tot;
}

__global__ void k_scatter(const int* __restrict__ ei, const float* __restrict__ eattr) {
    int e = blockIdx.x * blockDim.x + threadIdx.x;
    if (e >= EE) return;
    int d = ei[EE + e];
    int pos = g_rowptr[d] + atomicAdd(&g_cursor[d], 1);
    g_csr_src[pos] = ei[e];
    const float4* srcp = reinterpret_cast<const float4*>(&eattr[(size_t)e * EDD]);
    float4* dstp = reinterpret_cast<float4*>(&g_eaperm[(size_t)pos * EDD]);
    dstp[0] = srcp[0];
    dstp[1] = srcp[1];
    dstp[2] = srcp[2];
    dstp[3] = srcp[3];
}

// ---------------- per-layer prep: Wc, hb, bias2, BN-zero ----------------
__global__ void k_prep(const float* __restrict__ We_l, const float* __restrict__ be_l,
                       const float* __restrict__ Wpre_l, const float* __restrict__ bpre_l,
                       const float* __restrict__ Wlin_l, const float* __restrict__ bpost_l,
                       const float* __restrict__ blin_l) {
    int tid = threadIdx.x;
    if (tid < FF) { g_bnsum[tid] = 0.f; g_bnsq[tid] = 0.f; }
    for (int idx = tid; idx < EDD * FF; idx += 256) {
        int j = idx / FF, f = idx % FF;
        float s = 0.f;
        for (int m = 0; m < FF; m++)
            s += We_l[j * FF + m] * Wpre_l[(128 + m) * FF + f];
        g_Wc[idx] = s;
    }
    if (tid < FF) {
        float s = bpre_l[tid];
        for (int m = 0; m < FF; m++)
            s += be_l[m] * Wpre_l[(128 + m) * FF + tid];
        g_hb[tid] = s;
        float b = blin_l[tid];
        for (int m = 0; m < FF; m++)
            b += bpost_l[m] * Wlin_l[m * 64 + tid];
        g_bias2[tid] = b;
    }
}

// ---- fused pack + Wlin-fold + bf16 split/transpose: Bth/Btl directly ----
__global__ void k_packB(const float* __restrict__ Wpost_l, const float* __restrict__ Wlin_l) {
    int idx = blockIdx.x * blockDim.x + threadIdx.x;
    if (idx >= 320 * 192) return;
    int k = idx / 192, c = idx % 192;
    int blk = c >> 6, cc = c & 63;
    float s = 0.f;
    if (k < 64) {
        if (blk == 0) {
            const float* wrow = &Wpost_l[k * 64];
#pragma unroll 8
            for (int m = 0; m < 64; m++)
                s += wrow[m] * __ldg(&Wlin_l[m * 64 + cc]);
        }
    } else {
        const float* wrow = &Wpost_l[(64 + blk * 256 + (k - 64)) * 64];
#pragma unroll 8
        for (int m = 0; m < 64; m++)
            s += wrow[m] * __ldg(&Wlin_l[m * 64 + cc]);
    }
    __nv_bfloat16 h = __float2bfloat16_rn(s);
    __nv_bfloat16 l = __float2bfloat16_rn(s - __bfloat162float(h));
    g_Bth[c * 320 + k] = h;
    g_Btl[c * 320 + k] = l;
}

__global__ void k_cvtW(const float* __restrict__ Wpre_l) {
    int idx = blockIdx.x * blockDim.x + threadIdx.x;
    if (idx >= 128 * 64) return;
    int c = idx >> 6, k = idx & 63;
    float v = (c < 64) ? Wpre_l[k * 64 + c] : Wpre_l[(64 + k) * 64 + (c - 64)];
    __nv_bfloat16 h = __float2bfloat16_rn(v);
    __nv_bfloat16 l = __float2bfloat16_rn(v - __bfloat162float(h));
    g_Wth[c * 64 + k] = h;
    g_Wtl[c * 64 + k] = l;
}

__global__ void k_cvtX(const float* __restrict__ X) {
    int gid = blockIdx.x * blockDim.x + threadIdx.x;
    if (gid >= NN * 16) return;
    int r = gid >> 4, q = gid & 15;
    float4 v = *reinterpret_cast<const float4*>(&X[(size_t)r * 64 + q * 4]);
    u32 h0, l0, h1, l1;
    bfsplit2(v.x, v.y, h0, l0);
    bfsplit2(v.z, v.w, h1, l1);
    *reinterpret_cast<u64*>(&g_Ah[(size_t)r * 320 + q * 4]) = (u64)h0 | ((u64)h1 << 32);
    *reinterpret_cast<u64*>(&g_Al[(size_t)r * 320 + q * 4]) = (u64)l0 | ((u64)l1 << 32);
}

// ================= pipelined TC GEMM machinery =================
#define PITCH 40

__device__ __forceinline__ void stageA(__nv_bfloat16* sAh, __nv_bfloat16* sAl,
                                       int row0, int kc, int tid) {
#pragma unroll
    for (int it = 0; it < 2; it++) {
        int idx = tid + it * 128;
        int r = idx >> 2, q = idx & 3;
        int n = row0 + r;
        int nc = (n < NN) ? n : (NN - 1);
        int sz = (n < NN) ? 16 : 0;
        cpa16(s2u(sAh + r * PITCH + q * 8), &g_Ah[(size_t)nc * 320 + kc + q * 8], sz);
        cpa16(s2u(sAl + r * PITCH + q * 8), &g_Al[(size_t)nc * 320 + kc + q * 8], sz);
    }
}
__device__ __forceinline__ void stageB(__nv_bfloat16* sBh, __nv_bfloat16* sBl,
                                       const __nv_bfloat16* Bh, const __nv_bfloat16* Bl,
                                       int bstride, int c0, int kc, int tid) {
#pragma unroll
    for (int it = 0; it < 2; it++) {
        int idx = tid + it * 128;
        int r = idx >> 2, q = idx & 3;
        cpa16(s2u(sBh + r * PITCH + q * 8), &Bh[(size_t)(c0 + r) * bstride + kc + q * 8], 16);
        cpa16(s2u(sBl + r * PITCH + q * 8), &Bl[(size_t)(c0 + r) * bstride + kc + q * 8], 16);
    }
}
// stage 128 B-rows (for fused PQ)
__device__ __forceinline__ void stageB128(__nv_bfloat16* sBh, __nv_bfloat16* sBl,
                                          int kc, int tid) {
#pragma unroll
    for (int it = 0; it < 4; it++) {
        int idx = tid + it * 128;
        int r = idx >> 2, q = idx & 3;
        cpa16(s2u(sBh + r * PITCH + q * 8), &g_Wth[r * 64 + kc + q * 8], 16);
        cpa16(s2u(sBl + r * PITCH + q * 8), &g_Wtl[r * 64 + kc + q * 8], 16);
    }
}

// one 32-k chunk, NJ 8-col groups
template<int NJ>
__device__ __forceinline__ void tcchunkN(const __nv_bfloat16* sAh, const __nv_bfloat16* sAl,
                                         const __nv_bfloat16* sBh, const __nv_bfloat16* sBl,
                                         int m0, int n0l, int g, int t, float acc[][NJ][4]) {
#pragma unroll
    for (int kk = 0; kk < 32; kk += 16) {
        u32 ah[2][4], al[2][4];
#pragma unroll
        for (int mi = 0; mi < 2; mi++) {
            int r = m0 + mi * 16 + g;
            int cA = kk + 2 * t;
            ah[mi][0] = *reinterpret_cast<const u32*>(&sAh[r * PITCH + cA]);
            ah[mi][1] = *reinterpret_cast<const u32*>(&sAh[(r + 8) * PITCH + cA]);
            ah[mi][2] = *reinterpret_cast<const u32*>(&sAh[r * PITCH + cA + 8]);
            ah[mi][3] = *reinterpret_cast<const u32*>(&sAh[(r + 8) * PITCH + cA + 8]);
            al[mi][0] = *reinterpret_cast<const u32*>(&sAl[r * PITCH + cA]);
            al[mi][1] = *reinterpret_cast<const u32*>(&sAl[(r + 8) * PITCH + cA]);
            al[mi][2] = *reinterpret_cast<const u32*>(&sAl[r * PITCH + cA + 8]);
            al[mi][3] = *reinterpret_cast<const u32*>(&sAl[(r + 8) * PITCH + cA + 8]);
        }
#pragma unroll
        for (int j = 0; j < NJ; j++) {
            int nr = n0l + 8 * j + g;
            int cB = kk + 2 * t;
            u32 bh[2], bl[2];
            bh[0] = *reinterpret_cast<const u32*>(&sBh[nr * PITCH + cB]);
            bh[1] = *reinterpret_cast<const u32*>(&sBh[nr * PITCH + cB + 8]);
            bl[0] = *reinterpret_cast<const u32*>(&sBl[nr * PITCH + cB]);
            bl[1] = *reinterpret_cast<const u32*>(&sBl[nr * PITCH + cB + 8]);
#pragma unroll
            for (int mi = 0; mi < 2; mi++) {
                mma16816(acc[mi][j], ah[mi], bh);
                mma16816(acc[mi][j], ah[mi], bl);
                mma16816(acc[mi][j], al[mi], bh);
            }
        }
    }
}

// ---- main GEMM: C[N,192] = A @ B2 ; grid (782, 3), 128 thr ----
__global__ void __launch_bounds__(128) k_gemm_tc() {
    __shared__ __nv_bfloat16 sAh[2][64 * PITCH];
    __shared__ __nv_bfloat16 sAl[2][64 * PITCH];
    __shared__ __nv_bfloat16 sBh[2][64 * PITCH];
    __shared__ __nv_bfloat16 sBl[2][64 * PITCH];
    int tid = threadIdx.x;
    int warp = tid >> 5, lane = tid & 31;
    int g = lane >> 2, t = lane & 3;
    int wm = warp >> 1, wn = warp & 1;
    int m0 = wm * 32, n0l = wn * 32;
    int row0 = blockIdx.x * 64;
    int c0 = blockIdx.y * 64;
    float acc[2][4][4];
#pragma unroll
    for (int mi = 0; mi < 2; mi++)
#pragma unroll
        for (int j = 0; j < 4; j++)
#pragma unroll
            for (int q = 0; q < 4; q++) acc[mi][j][q] = 0.f;

    stageA(sAh[0], sAl[0], row0, 0, tid);
    stageB(sBh[0], sBl[0], g_Bth, g_Btl, 320, c0, 0, tid);
    CP_COMMIT;
    for (int i = 0; i < 10; i++) {
        int s = i & 1;
        if (i + 1 < 10) {
            stageA(sAh[s ^ 1], sAl[s ^ 1], row0, (i + 1) * 32, tid);
            stageB(sBh[s ^ 1], sBl[s ^ 1], g_Bth, g_Btl, 320, c0, (i + 1) * 32, tid);
            CP_COMMIT;
            CP_WAIT1;
        } else {
            CP_WAIT0;
        }
        __syncthreads();
        tcchunkN<4>(sAh[s], sAl[s], sBh[s], sBl[s], m0, n0l, g, t, acc);
        __syncthreads();
    }
#pragma unroll
    for (int mi = 0; mi < 2; mi++) {
#pragma unroll
        for (int j = 0; j < 4; j++) {
            int r = row0 + m0 + mi * 16 + g;
            int c = c0 + n0l + 8 * j + 2 * t;
            if (r < NN)
                *reinterpret_cast<float2*>(&g_C[(size_t)r * 192 + c]) =
                    make_float2(acc[mi][j][0], acc[mi][j][1]);
            if (r + 8 < NN)
                *reinterpret_cast<float2*>(&g_C[(size_t)(r + 8) * 192 + c]) =
                    make_float2(acc[mi][j][2], acc[mi][j][3]);
        }
    }
}

// ---- fused PQ GEMM: [P|Q][N,128] = X @ Wt ; grid 782, 128 thr, dyn smem ----
__global__ void __launch_bounds__(128) k_pq_tc2() {
    extern __shared__ __nv_bfloat16 dsm[];
    __nv_bfloat16* sAh0 = dsm;                      // 64*PITCH
    __nv_bfloat16* sAh1 = sAh0 + 64 * PITCH;
    __nv_bfloat16* sAl0 = sAh1 + 64 * PITCH;
    __nv_bfloat16* sAl1 = sAl0 + 64 * PITCH;
    __nv_bfloat16* sBh0 = sAl1 + 64 * PITCH;        // 128*PITCH
    __nv_bfloat16* sBh1 = sBh0 + 128 * PITCH;
    __nv_bfloat16* sBl0 = sBh1 + 128 * PITCH;
    __nv_bfloat16* sBl1 = sBl0 + 128 * PITCH;
    __nv_bfloat16* sAh[2] = {sAh0, sAh1};
    __nv_bfloat16* sAl[2] = {sAl0, sAl1};
    __nv_bfloat16* sBh[2] = {sBh0, sBh1};
    __nv_bfloat16* sBl[2] = {sBl0, sBl1};
    int tid = threadIdx.x;
    int warp = tid >> 5, lane = tid & 31;
    int g = lane >> 2, t = lane & 3;
    int wm = warp >> 1, wn = warp & 1;      // wm: 2 row-groups; wn: 0->P, 1->Q
    int m0 = wm * 32, n0l = wn * 64;
    int row0 = blockIdx.x * 64;
    float acc[2][8][4];
#pragma unroll
    for (int mi = 0; mi < 2; mi++)
#pragma unroll
        for (int j = 0; j < 8; j++)
#pragma unroll
            for (int q = 0; q < 4; q++) acc[mi][j][q] = 0.f;

    stageA(sAh[0], sAl[0], row0, 0, tid);
    stageB128(sBh[0], sBl[0], 0, tid);
    CP_COMMIT;
#pragma unroll
    for (int i = 0; i < 2; i++) {
        int s = i & 1;
        if (i + 1 < 2) {
            stageA(sAh[1], sAl[1], row0, 32, tid);
            stageB128(sBh[1], sBl[1], 32, tid);
            CP_COMMIT;
            CP_WAIT1;
        } else {
            CP_WAIT0;
        }
        __syncthreads();
        tcchunkN<8>(sAh[s], sAl[s], sBh[s], sBl[s], m0, n0l, g, t, acc);
        __syncthreads();
    }
    float* dst = (wn == 0) ? g_P : g_Q;
#pragma unroll
    for (int mi = 0; mi < 2; mi++) {
#pragma unroll
        for (int j = 0; j < 8; j++) {
            int r = row0 + m0 + mi * 16 + g;
            int c = 8 * j + 2 * t;
            if (r < NN)
                *reinterpret_cast<float2*>(&dst[(size_t)r * 64 + c]) =
                    make_float2(acc[mi][j][0], acc[mi][j][1]);
            if (r + 8 < NN)
                *reinterpret_cast<float2*>(&dst[(size_t)(r + 8) * 64 + c]) =
                    make_float2(acc[mi][j][2], acc[mi][j][3]);
        }
    }
}
#define PQ2_SMEM ((4 * 64 + 4 * 128) * PITCH * 2)   // bytes = 61440

// ---------------- per-node aggregation (depth-2 Q prefetch) ----------------
__global__ void __launch_bounds__(256) k_agg() {
    int warp = (blockIdx.x * blockDim.x + threadIdx.x) >> 5;
    int lane = threadIdx.x & 31;
    if (warp >= NN) return;
    int n = warp;
    int fp = 2 * lane;
    u64 wc2[16];
#pragma unroll
    for (int k = 0; k < 16; k++) wc2[k] = *reinterpret_cast<const u64*>(&g_Wc[k * 64 + fp]);
    u64 base2 = fadd2(*reinterpret_cast<const u64*>(&g_P[(size_t)n * FF + fp]),
                      *reinterpret_cast<const u64*>(&g_hb[fp]));
    int s = g_rowptr[n], e = g_rowptr[n + 1];
    u64 sum2 = 0ull, sq2 = 0ull;
    float mn0 = 3.4e38f, mn1 = 3.4e38f, mx0 = -3.4e38f, mx1 = -3.4e38f;
    u64 q_a = 0ull, q_b = 0ull;
    if (s < e)
        q_a = *reinterpret_cast<const u64*>(&g_Q[(size_t)g_csr_src[s] * FF + fp]);
    if (s + 1 < e)
        q_b = *reinterpret_cast<const u64*>(&g_Q[(size_t)g_csr_src[s + 1] * FF + fp]);
    for (int i = s; i < e; i++) {
        u64 qv = q_a;
        q_a = q_b;
        if (i + 2 < e)
            q_b = *reinterpret_cast<const u64*>(&g_Q[(size_t)g_csr_src[i + 2] * FF + fp]);
        const float* ep = &g_eaperm[(size_t)i * EDD];
        float eav[16];
#pragma unroll
        for (int k = 0; k < 16; k += 4) {
            float4 v = *reinterpret_cast<const float4*>(ep + k);
            eav[k] = v.x; eav[k + 1] = v.y; eav[k + 2] = v.z; eav[k + 3] = v.w;
        }
        u64 hA = fadd2(base2, qv);
        u64 p0 = 0ull, p1 = 0ull;
#pragma unroll
        for (int k = 0; k < 8; k++) {
            p0 = ffma2(pk2(eav[2 * k], eav[2 * k]), wc2[2 * k], p0);
            p1 = ffma2(pk2(eav[2 * k + 1], eav[2 * k + 1]), wc2[2 * k + 1], p1);
        }
        u64 h2 = fadd2(hA, fadd2(p0, p1));
        sum2 = fadd2(sum2, h2);
        sq2 = ffma2(h2, h2, sq2);
        float2 h = up2(h2);
        mn0 = fminf(mn0, h.x); mx0 = fmaxf(mx0, h.x);
        mn1 = fminf(mn1, h.y); mx1 = fmaxf(mx1, h.y);
    }
    float deg = (float)(e - s);
    float degc = fmaxf(deg, 1.0f);
    float2 sum = up2(sum2), sq = up2(sq2);
    float mean0 = sum.x / degc, mean1 = sum.y / degc;
    float std0 = sqrtf(fmaxf(sq.x / degc - mean0 * mean0, 0.f) + 1e-5f);
    float std1 = sqrtf(fmaxf(sq.y / degc - mean1 * mean1, 0.f) + 1e-5f);
    if (deg == 0.f) { mn0 = 0.f; mx0 = 0.f; mn1 = 0.f; mx1 = 0.f; }
    __nv_bfloat16* ah = &g_Ah[(size_t)n * 320 + 64 + fp];
    __nv_bfloat16* al = &g_Al[(size_t)n * 320 + 64 + fp];
    u32 hi, lo;
    bfsplit2(mean0, mean1, hi, lo);
    *reinterpret_cast<u32*>(ah + 0)   = hi; *reinterpret_cast<u32*>(al + 0)   = lo;
    bfsplit2(mn0, mn1, hi, lo);
    *reinterpret_cast<u32*>(ah + 64)  = hi; *reinterpret_cast<u32*>(al + 64)  = lo;
    bfsplit2(mx0, mx1, hi, lo);
    *reinterpret_cast<u32*>(ah + 128) = hi; *reinterpret_cast<u32*>(al + 128) = lo;
    bfsplit2(std0, std1, hi, lo);
    *reinterpret_cast<u32*>(ah + 192) = hi; *reinterpret_cast<u32*>(al + 192) = lo;
}

// ---------------- elementwise combine + BN stats ----------------
__global__ void __launch_bounds__(256) k_post() {
    int f = threadIdx.x & 63;
    int g = threadIdx.x >> 6;
    __shared__ float sred[256];
    float b2v = g_bias2[f];
    float ys = 0.f, yq = 0.f;
    int n0 = blockIdx.x * 64;
    for (int it = 0; it < 16; it++) {
        int n = n0 + it * 4 + g;
        if (n < NN) {
            const float* c = &g_C[(size_t)n * 192];
            float y = c[f] + g_amp[n] * c[64 + f] + g_att[n] * c[128 + f] + b2v;
            g_y[(size_t)n * FF + f] = y;
            ys += y;
            yq = fmaf(y, y, yq);
        }
    }
    sred[threadIdx.x] = ys;
    __syncthreads();
    if (threadIdx.x < 64) {
        float s = sred[f] + sred[64 + f] + sred[128 + f] + sred[192 + f];
        atomicAdd(&g_bnsum[f], s);
    }
    __syncthreads();
    sred[threadIdx.x] = yq;
    __syncthreads();
    if (threadIdx.x < 64) {
        float s = sred[f] + sred[64 + f] + sred[128 + f] + sred[192 + f];
        atomicAdd(&g_bnsq[f], s);
    }
}

__global__ void k_bnfin(const float* __restrict__ gamma_l, const float* __restrict__ beta_l) {
    int f = threadIdx.x;
    if (f >= FF) return;
    float mu = g_bnsum[f] / (float)NN;
    float var = g_bnsq[f] / (float)NN - mu * mu;
    float rs = rsqrtf(var + 1e-5f);
    float a = rs * gamma_l[f];
    g_bnA[f] = a;
    g_bnB[f] = beta_l[f] - mu * a;
}

__global__ void k_bnapply() {
    int gid = blockIdx.x * blockDim.x + threadIdx.x;
    if (gid >= NN * 16) return;
    int r = gid >> 4, q = gid & 15;
    int f0 = q * 4;
    float4 y = *reinterpret_cast<const float4*>(&g_y[(size_t)r * 64 + f0]);
    float v0 = fmaxf(y.x * g_bnA[f0 + 0] + g_bnB[f0 + 0], 0.f);
    float v1 = fmaxf(y.y * g_bnA[f0 + 1] + g_bnB[f0 + 1], 0.f);
    float v2 = fmaxf(y.z * g_bnA[f0 + 2] + g_bnB[f0 + 2], 0.f);
    float v3 = fmaxf(y.w * g_bnA[f0 + 3] + g_bnB[f0 + 3], 0.f);
    u32 h0, l0, h1, l1;
    bfsplit2(v0, v1, h0, l0);
    bfsplit2(v2, v3, h1, l1);
    *reinterpret_cast<u64*>(&g_Ah[(size_t)r * 320 + f0]) = (u64)h0 | ((u64)h1 << 32);
    *reinterpret_cast<u64*>(&g_Al[(size_t)r * 320 + f0]) = (u64)l0 | ((u64)l1 << 32);
}

__global__ void k_bnpool(const int* __restrict__ batch) {
    int gid = blockIdx.x * blockDim.x + threadIdx.x;
    if (gid >= NN * FF) return;
    int n = gid >> 6, f = gid & 63;
    float v = fmaxf(g_y[gid] * g_bnA[f] + g_bnB[f], 0.f);
    int b = batch[n];
    atomicAdd(&g_gsum[b * FF + f], v);
    if (f == 0) atomicAdd(&g_gcnt[b], 1);
}

__global__ void k_head(const float* __restrict__ W1, const float* __restrict__ b1,
                       const float* __restrict__ W2, const float* __restrict__ b2,
                       float* __restrict__ out) {
    int g = threadIdx.x;
    if (g >= GG) return;
    float cnt = fmaxf((float)g_gcnt[g], 1.0f);
    float inv = 1.0f / cnt;
    float gm[64];
#pragma unroll
    for (int k = 0; k < 64; k++) gm[k] = g_gsum[g * FF + k] * inv;
    float o = b2[0];
    for (int j = 0; j < 40; j++) {
        float s = b1[j];
#pragma unroll
        for (int k = 0; k < 64; k++) s = fmaf(gm[k], W1[k * 40 + j], s);
        o = fmaf(fmaxf(s, 0.f), W2[j], o);
    }
    out[g] = o;
}

// ---------------- launch ----------------
extern "C" void kernel_launch(void* const* d_in, const int* in_sizes, int n_in,
                              void* d_out, int out_size) {
    const float* x     = (const float*)d_in[0];
    const float* ea    = (const float*)d_in[1];
    const float* We    = (const float*)d_in[2];
    const float* be    = (const float*)d_in[3];
    const float* Wpre  = (const float*)d_in[4];
    const float* bpre  = (const float*)d_in[5];
    const float* Wpost = (const float*)d_in[6];
    const float* bpost = (const float*)d_in[7];
    const float* Wlin  = (const float*)d_in[8];
    const float* blin  = (const float*)d_in[9];
    const float* gamma = (const float*)d_in[10];
    const float* beta  = (const float*)d_in[11];
    const float* W1    = (const float*)d_in[12];
    const float* b1    = (const float*)d_in[13];
    const float* W2    = (const float*)d_in[14];
    const float* b2    = (const float*)d_in[15];
    const int*   ei    = (const int*)d_in[16];
    const int*   batch = (const int*)d_in[17];
    float* out = (float*)d_out;

    cudaFuncSetAttribute(k_pq_tc2, cudaFuncAttributeMaxDynamicSharedMemorySize, PQ2_SMEM);

    dim3 ggm((NN + 63) / 64, 3);
    int gpq = (NN + 63) / 64;

    k_init<<<256, 256>>>();                              // idx 0
    k_cvtX<<<(NN * 16 + 255) / 256, 256>>>(x);           // idx 1
    k_cvtW<<<(128 * 64 + 255) / 256, 256>>>(Wpre);       // idx 2
    k_pq_tc2<<<gpq, 128, PQ2_SMEM>>>();                  // idx 3  <- PROFILED
    k_deg<<<(EE + 255) / 256, 256>>>(ei);                // idx 4
    k_scan1<<<SCB, 1024>>>();                            // idx 5
    k_scan3<<<SCB, 1024>>>();                            // idx 6
    k_scatter<<<(EE + 255) / 256, 256>>>(ei, ea);        // idx 7

    for (int l = 0; l < LL; l++) {
        k_prep<<<1, 256>>>(We + l * EDD * FF, be + l * FF, Wpre + l * 192 * FF, bpre + l * FF,
                           Wlin + l * FF * FF, bpost + l * FF, blin + l * FF);
        k_packB<<<(320 * 192 + 255) / 256, 256>>>(Wpost + l * 832 * FF, Wlin + l * FF * FF);
        if (l > 0) {
            k_cvtW<<<(128 * 64 + 255) / 256, 256>>>(Wpre + l * 192 * FF);
            k_pq_tc2<<<gpq, 128, PQ2_SMEM>>>();
        }
        k_agg<<<(NN + 7) / 8, 256>>>();
        k_gemm_tc<<<ggm, 128>>>();
        k_post<<<(NN + 63) / 64, 256>>>();
        k_bnfin<<<1, 64>>>(gamma + l * FF, beta + l * FF);
        if (l == 0) k_bnapply<<<(NN * 16 + 255) / 256, 256>>>();
        else        k_bnpool<<<(NN * FF + 255) / 256, 256>>>(batch);
    }

    k_head<<<1, 64>>>(W1, b1, W2, b2, out);
}

// round 14
// speedup vs baseline: 1.0736x; 1.0736x over previous
#include <cuda_runtime.h>
#include <cuda_bf16.h>
#include <math.h>
#include <stddef.h>

#define NN 50000
#define EE 800000
#define FF 64
#define EDD 16
#define GG 64
#define LL 2
#define SCB ((NN + 1023) / 1024)

typedef unsigned long long u64;
typedef unsigned int u32;

// ---------------- packed f32x2 helpers ----------------
__device__ __forceinline__ u64 pk2(float x, float y) {
    u64 r; asm("mov.b64 %0,{%1,%2};" : "=l"(r) : "f"(x), "f"(y)); return r;
}
__device__ __forceinline__ float2 up2(u64 v) {
    float2 r; asm("mov.b64 {%0,%1},%2;" : "=f"(r.x), "=f"(r.y) : "l"(v)); return r;
}
__device__ __forceinline__ u64 ffma2(u64 a, u64 b, u64 c) {
    u64 d; asm("fma.rn.f32x2 %0,%1,%2,%3;" : "=l"(d) : "l"(a), "l"(b), "l"(c)); return d;
}
__device__ __forceinline__ u64 fadd2(u64 a, u64 b) {
    u64 d; asm("add.rn.f32x2 %0,%1,%2;" : "=l"(d) : "l"(a), "l"(b)); return d;
}

// ---------------- bf16 / mma / cp.async helpers ----------------
__device__ __forceinline__ void mma16816(float* d, const u32* a, const u32* b) {
    asm volatile("mma.sync.aligned.m16n8k16.row.col.f32.bf16.bf16.f32 "
                 "{%0,%1,%2,%3},{%4,%5,%6,%7},{%8,%9},{%0,%1,%2,%3};"
                 : "+f"(d[0]), "+f"(d[1]), "+f"(d[2]), "+f"(d[3])
                 : "r"(a[0]), "r"(a[1]), "r"(a[2]), "r"(a[3]), "r"(b[0]), "r"(b[1]));
}
__device__ __forceinline__ void bfsplit2(float a, float b, u32& hi, u32& lo) {
    __nv_bfloat16 ah = __float2bfloat16_rn(a);
    __nv_bfloat16 bh = __float2bfloat16_rn(b);
    __nv_bfloat16 al = __float2bfloat16_rn(a - __bfloat162float(ah));
    __nv_bfloat16 bl = __float2bfloat16_rn(b - __bfloat162float(bh));
    unsigned short ahs = *reinterpret_cast<unsigned short*>(&ah);
    unsigned short bhs = *reinterpret_cast<unsigned short*>(&bh);
    unsigned short als = *reinterpret_cast<unsigned short*>(&al);
    unsigned short bls = *reinterpret_cast<unsigned short*>(&bl);
    hi = (u32)ahs | ((u32)bhs << 16);
    lo = (u32)als | ((u32)bls << 16);
}
__device__ __forceinline__ u32 s2u(const void* p) {
    return (u32)__cvta_generic_to_shared(p);
}
__device__ __forceinline__ void cpa16(u32 dst, const void* src, int sz) {
    asm volatile("cp.async.cg.shared.global [%0],[%1],16,%2;" :: "r"(dst), "l"(src), "r"(sz));
}
#define CP_COMMIT asm volatile("cp.async.commit_group;")
#define CP_WAIT1  asm volatile("cp.async.wait_group 1;")
#define CP_WAIT0  asm volatile("cp.async.wait_group 0;")

// ---------------- scratch ----------------
__device__ int   g_deg[NN];
__device__ int   g_rowptr[NN + 1];
__device__ int   g_cursor[NN];
__device__ int   g_bsum[64];
__device__ int   g_csr_src[EE];
__device__ float g_eaperm[(size_t)EE * EDD];
__device__ float g_amp[NN];
__device__ float g_att[NN];
__device__ float g_logsum;
__device__ float g_P[NN * FF];
__device__ float g_Q[NN * FF];
__device__ float g_Wc[EDD * FF];
__device__ float g_hb[FF];
__device__ float g_bias2[FF];
__device__ float g_y[NN * FF];
__device__ float g_bnsum[FF];
__device__ float g_bnsq[FF];
__device__ float g_bnA[FF];
__device__ float g_bnB[FF];
__device__ float g_gsum[GG * FF];
__device__ int   g_gcnt[GG];
__device__ __nv_bfloat16 g_Ah[(size_t)NN * 320];
__device__ __nv_bfloat16 g_Al[(size_t)NN * 320];
__device__ __nv_bfloat16 g_Bth[192 * 320];
__device__ __nv_bfloat16 g_Btl[192 * 320];
__device__ __nv_bfloat16 g_Wth[128 * 64];
__device__ __nv_bfloat16 g_Wtl[128 * 64];

// ---------------- init / degree / CSR ----------------
__global__ void k_init() {
    int i  = blockIdx.x * blockDim.x + threadIdx.x;
    int nt = gridDim.x * blockDim.x;
    for (int j = i; j < NN; j += nt) { g_deg[j] = 0; g_cursor[j] = 0; }
    for (int j = i; j < GG * FF; j += nt) g_gsum[j] = 0.f;
    if (i < GG) g_gcnt[i] = 0;
    if (i == 0) g_logsum = 0.f;
}

__global__ void k_deg(const int* __restrict__ ei) {
    int e = blockIdx.x * blockDim.x + threadIdx.x;
    if (e < EE) atomicAdd(&g_deg[ei[EE + e]], 1);
}

__global__ void k_scan1() {
    int tid = threadIdx.x, lane = tid & 31, wid = tid >> 5;
    int i = blockIdx.x * 1024 + tid;
    int v = (i < NN) ? g_deg[i] : 0;
    float lv = (i < NN) ? logf((float)v + 1.0f) : 0.0f;
#pragma unroll
    for (int off = 16; off > 0; off >>= 1) lv += __shfl_xor_sync(0xffffffffu, lv, off);
    if (lane == 0) atomicAdd(&g_logsum, lv);
    int x = v;
#pragma unroll
    for (int off = 1; off < 32; off <<= 1) {
        int t = __shfl_up_sync(0xffffffffu, x, off);
        if (lane >= off) x += t;
    }
    __shared__ int ws[32];
    if (lane == 31) ws[wid] = x;
    __syncthreads();
    if (wid == 0) {
        int s = ws[lane];
#pragma unroll
        for (int off = 1; off < 32; off <<= 1) {
            int t = __shfl_up_sync(0xffffffffu, s, off);
            if (lane >= off) s += t;
        }
        ws[lane] = s;
    }
    __syncthreads();
    int wbase = wid ? ws[wid - 1] : 0;
    if (i < NN) g_rowptr[i] = wbase + x - v;
    if (tid == 1023) g_bsum[blockIdx.x] = wbase + x;
}

__global__ void k_scan3() {
    __shared__ int sb[64];
    __shared__ int s_off, s_tot;
    int t = threadIdx.x;
    if (t < 64) sb[t] = (t < SCB) ? g_bsum[t] : 0;
    __syncthreads();
    if (t == 0) {
        int off = 0, tot = 0;
        for (int j = 0; j < SCB; j++) {
            if (j < (int)blockIdx.x) off += sb[j];
            tot += sb[j];
        }
        s_off = off; s_tot = tot;
    }
    __syncthreads();
    int i = blockIdx.x * 1024 + t;
    if (i < NN) {
        g_rowptr[i] += s_off;
        float avg = g_logsum / (float)NN;
        float d = (float)g_deg[i];
        float logd = logf(fmaxf(d, 1.0f) + 1.0f);
        g_amp[i] = logd / avg;
        g_att[i] = avg / logd;
    }
    if (blockIdx.x == gridDim.x - 1 && t == 0) g_rowptr[NN] = s_tot;
}

__global__ void k_scatter(const int* __restrict__ ei, const float* __restrict__ eattr) {
    int e = blockIdx.x * blockDim.x + threadIdx.x;
    if (e >= EE) return;
    int d = ei[EE + e];
    int pos = g_rowptr[d] + atomicAdd(&g_cursor[d], 1);
    g_csr_src[pos] = ei[e];
    const float4* srcp = reinterpret_cast<const float4*>(&eattr[(size_t)e * EDD]);
    float4* dstp = reinterpret_cast<float4*>(&g_eaperm[(size_t)pos * EDD]);
    dstp[0] = srcp[0];
    dstp[1] = srcp[1];
    dstp[2] = srcp[2];
    dstp[3] = srcp[3];
}

// ---------------- per-layer prep: Wc, hb, bias2, BN-zero ----------------
__global__ void k_prep(const float* __restrict__ We_l, const float* __restrict__ be_l,
                       const float* __restrict__ Wpre_l, const float* __restrict__ bpre_l,
                       const float* __restrict__ Wlin_l, const float* __restrict__ bpost_l,
                       const float* __restrict__ blin_l) {
    int tid = threadIdx.x;
    if (tid < FF) { g_bnsum[tid] = 0.f; g_bnsq[tid] = 0.f; }
    for (int idx = tid; idx < EDD * FF; idx += 256) {
        int j = idx / FF, f = idx % FF;
        float s = 0.f;
        for (int m = 0; m < FF; m++)
            s += We_l[j * FF + m] * Wpre_l[(128 + m) * FF + f];
        g_Wc[idx] = s;
    }
    if (tid < FF) {
        float s = bpre_l[tid];
        for (int m = 0; m < FF; m++)
            s += be_l[m] * Wpre_l[(128 + m) * FF + tid];
        g_hb[tid] = s;
        float b = blin_l[tid];
        for (int m = 0; m < FF; m++)
            b += bpost_l[m] * Wlin_l[m * 64 + tid];
        g_bias2[tid] = b;
    }
}

// ---- fused pack + Wlin-fold + bf16 split/transpose ----
__global__ void k_packB(const float* __restrict__ Wpost_l, const float* __restrict__ Wlin_l) {
    int idx = blockIdx.x * blockDim.x + threadIdx.x;
    if (idx >= 320 * 192) return;
    int k = idx / 192, c = idx % 192;
    int blk = c >> 6, cc = c & 63;
    float s = 0.f;
    if (k < 64) {
        if (blk == 0) {
            const float* wrow = &Wpost_l[k * 64];
#pragma unroll 8
            for (int m = 0; m < 64; m++)
                s += wrow[m] * __ldg(&Wlin_l[m * 64 + cc]);
        }
    } else {
        const float* wrow = &Wpost_l[(64 + blk * 256 + (k - 64)) * 64];
#pragma unroll 8
        for (int m = 0; m < 64; m++)
            s += wrow[m] * __ldg(&Wlin_l[m * 64 + cc]);
    }
    __nv_bfloat16 h = __float2bfloat16_rn(s);
    __nv_bfloat16 l = __float2bfloat16_rn(s - __bfloat162float(h));
    g_Bth[c * 320 + k] = h;
    g_Btl[c * 320 + k] = l;
}

__global__ void k_cvtW(const float* __restrict__ Wpre_l) {
    int idx = blockIdx.x * blockDim.x + threadIdx.x;
    if (idx >= 128 * 64) return;
    int c = idx >> 6, k = idx & 63;
    float v = (c < 64) ? Wpre_l[k * 64 + c] : Wpre_l[(64 + k) * 64 + (c - 64)];
    __nv_bfloat16 h = __float2bfloat16_rn(v);
    __nv_bfloat16 l = __float2bfloat16_rn(v - __bfloat162float(h));
    g_Wth[c * 64 + k] = h;
    g_Wtl[c * 64 + k] = l;
}

__global__ void k_cvtX(const float* __restrict__ X) {
    int gid = blockIdx.x * blockDim.x + threadIdx.x;
    if (gid >= NN * 16) return;
    int r = gid >> 4, q = gid & 15;
    float4 v = *reinterpret_cast<const float4*>(&X[(size_t)r * 64 + q * 4]);
    u32 h0, l0, h1, l1;
    bfsplit2(v.x, v.y, h0, l0);
    bfsplit2(v.z, v.w, h1, l1);
    *reinterpret_cast<u64*>(&g_Ah[(size_t)r * 320 + q * 4]) = (u64)h0 | ((u64)h1 << 32);
    *reinterpret_cast<u64*>(&g_Al[(size_t)r * 320 + q * 4]) = (u64)l0 | ((u64)l1 << 32);
}

// ================= pipelined TC GEMM machinery =================
#define PITCH 40

__device__ __forceinline__ void stageA(__nv_bfloat16* sAh, __nv_bfloat16* sAl,
                                       int row0, int kc, int tid) {
#pragma unroll
    for (int it = 0; it < 2; it++) {
        int idx = tid + it * 128;
        int r = idx >> 2, q = idx & 3;
        int n = row0 + r;
        int nc = (n < NN) ? n : (NN - 1);
        int sz = (n < NN) ? 16 : 0;
        cpa16(s2u(sAh + r * PITCH + q * 8), &g_Ah[(size_t)nc * 320 + kc + q * 8], sz);
        cpa16(s2u(sAl + r * PITCH + q * 8), &g_Al[(size_t)nc * 320 + kc + q * 8], sz);
    }
}
// stage all 192 B c-rows of one 32-k chunk
__device__ __forceinline__ void stageB192(__nv_bfloat16* sBh, __nv_bfloat16* sBl,
                                          int kc, int tid) {
#pragma unroll
    for (int it = 0; it < 6; it++) {
        int idx = tid + it * 128;
        int r = idx >> 2, q = idx & 3;
        cpa16(s2u(sBh + r * PITCH + q * 8), &g_Bth[(size_t)r * 320 + kc + q * 8], 16);
        cpa16(s2u(sBl + r * PITCH + q * 8), &g_Btl[(size_t)r * 320 + kc + q * 8], 16);
    }
}
// stage 128 B-rows (PQ weights)
__device__ __forceinline__ void stageB128(__nv_bfloat16* sBh, __nv_bfloat16* sBl,
                                          int kc, int tid) {
#pragma unroll
    for (int it = 0; it < 4; it++) {
        int idx = tid + it * 128;
        int r = idx >> 2, q = idx & 3;
        cpa16(s2u(sBh + r * PITCH + q * 8), &g_Wth[r * 64 + kc + q * 8], 16);
        cpa16(s2u(sBl + r * PITCH + q * 8), &g_Wtl[r * 64 + kc + q * 8], 16);
    }
}

template<int NJ>
__device__ __forceinline__ void tcchunkN(const __nv_bfloat16* sAh, const __nv_bfloat16* sAl,
                                         const __nv_bfloat16* sBh, const __nv_bfloat16* sBl,
                                         int m0, int n0l, int g, int t, float acc[][NJ][4]) {
#pragma unroll
    for (int kk = 0; kk < 32; kk += 16) {
        u32 ah[2][4], al[2][4];
#pragma unroll
        for (int mi = 0; mi < 2; mi++) {
            int r = m0 + mi * 16 + g;
            int cA = kk + 2 * t;
            ah[mi][0] = *reinterpret_cast<const u32*>(&sAh[r * PITCH + cA]);
            ah[mi][1] = *reinterpret_cast<const u32*>(&sAh[(r + 8) * PITCH + cA]);
            ah[mi][2] = *reinterpret_cast<const u32*>(&sAh[r * PITCH + cA + 8]);
            ah[mi][3] = *reinterpret_cast<const u32*>(&sAh[(r + 8) * PITCH + cA + 8]);
            al[mi][0] = *reinterpret_cast<const u32*>(&sAl[r * PITCH + cA]);
            al[mi][1] = *reinterpret_cast<const u32*>(&sAl[(r + 8) * PITCH + cA]);
            al[mi][2] = *reinterpret_cast<const u32*>(&sAl[r * PITCH + cA + 8]);
            al[mi][3] = *reinterpret_cast<const u32*>(&sAl[(r + 8) * PITCH + cA + 8]);
        }
#pragma unroll
        for (int j = 0; j < NJ; j++) {
            int nr = n0l + 8 * j + g;
            int cB = kk + 2 * t;
            u32 bh[2], bl[2];
            bh[0] = *reinterpret_cast<const u32*>(&sBh[nr * PITCH + cB]);
            bh[1] = *reinterpret_cast<const u32*>(&sBh[nr * PITCH + cB + 8]);
            bl[0] = *reinterpret_cast<const u32*>(&sBl[nr * PITCH + cB]);
            bl[1] = *reinterpret_cast<const u32*>(&sBl[nr * PITCH + cB + 8]);
#pragma unroll
            for (int mi = 0; mi < 2; mi++) {
                mma16816(acc[mi][j], ah[mi], bh);
                mma16816(acc[mi][j], ah[mi], bl);
                mma16816(acc[mi][j], al[mi], bh);
            }
        }
    }
}

// ---- fused main GEMM + combine: y[N,64] ; grid 782, 128 thr, dyn smem ----
__global__ void __launch_bounds__(128) k_gemm_tc2() {
    extern __shared__ __nv_bfloat16 dsm[];
    __nv_bfloat16* sAh[2] = {dsm, dsm + 64 * PITCH};
    __nv_bfloat16* sAl[2] = {dsm + 2 * 64 * PITCH, dsm + 3 * 64 * PITCH};
    __nv_bfloat16* base = dsm + 4 * 64 * PITCH;
    __nv_bfloat16* sBh[2] = {base, base + 192 * PITCH};
    __nv_bfloat16* sBl[2] = {base + 2 * 192 * PITCH, base + 3 * 192 * PITCH};
    int tid = threadIdx.x;
    int warp = tid >> 5, lane = tid & 31;
    int g = lane >> 2, t = lane & 3;
    int wm = warp >> 1, wn = warp & 1;
    int m0 = wm * 32, n0l = wn * 32;
    int row0 = blockIdx.x * 64;
    float acc[3][2][4][4];
#pragma unroll
    for (int cb = 0; cb < 3; cb++)
#pragma unroll
        for (int mi = 0; mi < 2; mi++)
#pragma unroll
            for (int j = 0; j < 4; j++)
#pragma unroll
                for (int q = 0; q < 4; q++) acc[cb][mi][j][q] = 0.f;

    stageA(sAh[0], sAl[0], row0, 0, tid);
    stageB192(sBh[0], sBl[0], 0, tid);
    CP_COMMIT;
    for (int i = 0; i < 10; i++) {
        int s = i & 1;
        if (i + 1 < 10) {
            stageA(sAh[s ^ 1], sAl[s ^ 1], row0, (i + 1) * 32, tid);
            stageB192(sBh[s ^ 1], sBl[s ^ 1], (i + 1) * 32, tid);
            CP_COMMIT;
            CP_WAIT1;
        } else {
            CP_WAIT0;
        }
        __syncthreads();
#pragma unroll
        for (int cb = 0; cb < 3; cb++)
            tcchunkN<4>(sAh[s], sAl[s], sBh[s] + cb * 64 * PITCH, sBl[s] + cb * 64 * PITCH,
                        m0, n0l, g, t, acc[cb]);
        __syncthreads();
    }
    // fused combine epilogue: y = C0 + amp*C1 + att*C2 + bias2
#pragma unroll
    for (int mi = 0; mi < 2; mi++) {
        int r0 = row0 + m0 + mi * 16 + g;
        int r1 = r0 + 8;
        float amp0 = (r0 < NN) ? g_amp[r0] : 0.f;
        float att0 = (r0 < NN) ? g_att[r0] : 0.f;
        float amp1 = (r1 < NN) ? g_amp[r1] : 0.f;
        float att1 = (r1 < NN) ? g_att[r1] : 0.f;
#pragma unroll
        for (int j = 0; j < 4; j++) {
            int c = n0l + 8 * j + 2 * t;
            float b0 = g_bias2[c], b1 = g_bias2[c + 1];
            if (r0 < NN) {
                float y0 = acc[0][mi][j][0] + amp0 * acc[1][mi][j][0] + att0 * acc[2][mi][j][0] + b0;
                float y1 = acc[0][mi][j][1] + amp0 * acc[1][mi][j][1] + att0 * acc[2][mi][j][1] + b1;
                *reinterpret_cast<float2*>(&g_y[(size_t)r0 * 64 + c]) = make_float2(y0, y1);
            }
            if (r1 < NN) {
                float y2 = acc[0][mi][j][2] + amp1 * acc[1][mi][j][2] + att1 * acc[2][mi][j][2] + b0;
                float y3 = acc[0][mi][j][3] + amp1 * acc[1][mi][j][3] + att1 * acc[2][mi][j][3] + b1;
                *reinterpret_cast<float2*>(&g_y[(size_t)r1 * 64 + c]) = make_float2(y2, y3);
            }
        }
    }
}
#define GM2_SMEM ((4 * 64 + 4 * 192) * PITCH * 2)   // 81920 bytes

// ---- fused PQ GEMM: [P|Q][N,128] = X @ Wt ; grid 782, 128 thr, dyn smem ----
__global__ void __launch_bounds__(128) k_pq_tc2() {
    extern __shared__ __nv_bfloat16 dsm[];
    __nv_bfloat16* sAh[2] = {dsm, dsm + 64 * PITCH};
    __nv_bfloat16* sAl[2] = {dsm + 2 * 64 * PITCH, dsm + 3 * 64 * PITCH};
    __nv_bfloat16* base = dsm + 4 * 64 * PITCH;
    __nv_bfloat16* sBh[2] = {base, base + 128 * PITCH};
    __nv_bfloat16* sBl[2] = {base + 2 * 128 * PITCH, base + 3 * 128 * PITCH};
    int tid = threadIdx.x;
    int warp = tid >> 5, lane = tid & 31;
    int g = lane >> 2, t = lane & 3;
    int wm = warp >> 1, wn = warp & 1;
    int m0 = wm * 32, n0l = wn * 64;
    int row0 = blockIdx.x * 64;
    float acc[2][8][4];
#pragma unroll
    for (int mi = 0; mi < 2; mi++)
#pragma unroll
        for (int j = 0; j < 8; j++)
#pragma unroll
            for (int q = 0; q < 4; q++) acc[mi][j][q] = 0.f;

    stageA(sAh[0], sAl[0], row0, 0, tid);
    stageB128(sBh[0], sBl[0], 0, tid);
    CP_COMMIT;
#pragma unroll
    for (int i = 0; i < 2; i++) {
        int s = i & 1;
        if (i + 1 < 2) {
            stageA(sAh[1], sAl[1], row0, 32, tid);
            stageB128(sBh[1], sBl[1], 32, tid);
            CP_COMMIT;
            CP_WAIT1;
        } else {
            CP_WAIT0;
        }
        __syncthreads();
        tcchunkN<8>(sAh[s], sAl[s], sBh[s], sBl[s], m0, n0l, g, t, acc);
        __syncthreads();
    }
    float* dst = (wn == 0) ? g_P : g_Q;
#pragma unroll
    for (int mi = 0; mi < 2; mi++) {
#pragma unroll
        for (int j = 0; j < 8; j++) {
            int r = row0 + m0 + mi * 16 + g;
            int c = 8 * j + 2 * t;
            if (r < NN)
                *reinterpret_cast<float2*>(&dst[(size_t)r * 64 + c]) =
                    make_float2(acc[mi][j][0], acc[mi][j][1]);
            if (r + 8 < NN)
                *reinterpret_cast<float2*>(&dst[(size_t)(r + 8) * 64 + c]) =
                    make_float2(acc[mi][j][2], acc[mi][j][3]);
        }
    }
}
#define PQ2_SMEM ((4 * 64 + 4 * 128) * PITCH * 2)   // 61440 bytes

// ---------------- per-node aggregation (R12 depth-1 form) ----------------
__global__ void __launch_bounds__(256) k_agg() {
    int warp = (blockIdx.x * blockDim.x + threadIdx.x) >> 5;
    int lane = threadIdx.x & 31;
    if (warp >= NN) return;
    int n = warp;
    int fp = 2 * lane;
    u64 wc2[16];
#pragma unroll
    for (int k = 0; k < 16; k++) wc2[k] = *reinterpret_cast<const u64*>(&g_Wc[k * 64 + fp]);
    u64 base2 = fadd2(*reinterpret_cast<const u64*>(&g_P[(size_t)n * FF + fp]),
                      *reinterpret_cast<const u64*>(&g_hb[fp]));
    int s = g_rowptr[n], e = g_rowptr[n + 1];
    u64 sum2 = 0ull, sq2 = 0ull;
    float mn0 = 3.4e38f, mn1 = 3.4e38f, mx0 = -3.4e38f, mx1 = -3.4e38f;
    int src_n = 0; u64 q_n = 0ull;
    if (s < e) {
        src_n = g_csr_src[s];
        q_n = *reinterpret_cast<const u64*>(&g_Q[(size_t)src_n * FF + fp]);
    }
    for (int i = s; i < e; i++) {
        u64 qv = q_n;
        if (i + 1 < e) {
            src_n = g_csr_src[i + 1];
            q_n = *reinterpret_cast<const u64*>(&g_Q[(size_t)src_n * FF + fp]);
        }
        const float* ep = &g_eaperm[(size_t)i * EDD];
        float eav[16];
#pragma unroll
        for (int k = 0; k < 16; k += 4) {
            float4 v = *reinterpret_cast<const float4*>(ep + k);
            eav[k] = v.x; eav[k + 1] = v.y; eav[k + 2] = v.z; eav[k + 3] = v.w;
        }
        u64 hA = fadd2(base2, qv);
        u64 p0 = 0ull, p1 = 0ull;
#pragma unroll
        for (int k = 0; k < 8; k++) {
            p0 = ffma2(pk2(eav[2 * k], eav[2 * k]), wc2[2 * k], p0);
            p1 = ffma2(pk2(eav[2 * k + 1], eav[2 * k + 1]), wc2[2 * k + 1], p1);
        }
        u64 h2 = fadd2(hA, fadd2(p0, p1));
        sum2 = fadd2(sum2, h2);
        sq2 = ffma2(h2, h2, sq2);
        float2 h = up2(h2);
        mn0 = fminf(mn0, h.x); mx0 = fmaxf(mx0, h.x);
        mn1 = fminf(mn1, h.y); mx1 = fmaxf(mx1, h.y);
    }
    float deg = (float)(e - s);
    float degc = fmaxf(deg, 1.0f);
    float2 sum = up2(sum2), sq = up2(sq2);
    float mean0 = sum.x / degc, mean1 = sum.y / degc;
    float std0 = sqrtf(fmaxf(sq.x / degc - mean0 * mean0, 0.f) + 1e-5f);
    float std1 = sqrtf(fmaxf(sq.y / degc - mean1 * mean1, 0.f) + 1e-5f);
    if (deg == 0.f) { mn0 = 0.f; mx0 = 0.f; mn1 = 0.f; mx1 = 0.f; }
    __nv_bfloat16* ah = &g_Ah[(size_t)n * 320 + 64 + fp];
    __nv_bfloat16* al = &g_Al[(size_t)n * 320 + 64 + fp];
    u32 hi, lo;
    bfsplit2(mean0, mean1, hi, lo);
    *reinterpret_cast<u32*>(ah + 0)   = hi; *reinterpret_cast<u32*>(al + 0)   = lo;
    bfsplit2(mn0, mn1, hi, lo);
    *reinterpret_cast<u32*>(ah + 64)  = hi; *reinterpret_cast<u32*>(al + 64)  = lo;
    bfsplit2(mx0, mx1, hi, lo);
    *reinterpret_cast<u32*>(ah + 128) = hi; *reinterpret_cast<u32*>(al + 128) = lo;
    bfsplit2(std0, std1, hi, lo);
    *reinterpret_cast<u32*>(ah + 192) = hi; *reinterpret_cast<u32*>(al + 192) = lo;
}

// ---------------- BN stats over y ----------------
__global__ void __launch_bounds__(256) k_bnstat() {
    int f = threadIdx.x & 63;
    int g = threadIdx.x >> 6;
    __shared__ float sred[256];
    float ys = 0.f, yq = 0.f;
    int n0 = blockIdx.x * 256;
    for (int it = 0; it < 64; it++) {
        int n = n0 + it * 4 + g;
        if (n < NN) {
            float y = g_y[(size_t)n * FF + f];
            ys += y;
            yq = fmaf(y, y, yq);
        }
    }
    sred[threadIdx.x] = ys;
    __syncthreads();
    if (threadIdx.x < 64) {
        float s = sred[f] + sred[64 + f] + sred[128 + f] + sred[192 + f];
        atomicAdd(&g_bnsum[f], s);
    }
    __syncthreads();
    sred[threadIdx.x] = yq;
    __syncthreads();
    if (threadIdx.x < 64) {
        float s = sred[f] + sred[64 + f] + sred[128 + f] + sred[192 + f];
        atomicAdd(&g_bnsq[f], s);
    }
}

__global__ void k_bnfin(const float* __restrict__ gamma_l, const float* __restrict__ beta_l) {
    int f = threadIdx.x;
    if (f >= FF) return;
    float mu = g_bnsum[f] / (float)NN;
    float var = g_bnsq[f] / (float)NN - mu * mu;
    float rs = rsqrtf(var + 1e-5f);
    float a = rs * gamma_l[f];
    g_bnA[f] = a;
    g_bnB[f] = beta_l[f] - mu * a;
}

__global__ void k_bnapply() {
    int gid = blockIdx.x * blockDim.x + threadIdx.x;
    if (gid >= NN * 16) return;
    int r = gid >> 4, q = gid & 15;
    int f0 = q * 4;
    float4 y = *reinterpret_cast<const float4*>(&g_y[(size_t)r * 64 + f0]);
    float v0 = fmaxf(y.x * g_bnA[f0 + 0] + g_bnB[f0 + 0], 0.f);
    float v1 = fmaxf(y.y * g_bnA[f0 + 1] + g_bnB[f0 + 1], 0.f);
    float v2 = fmaxf(y.z * g_bnA[f0 + 2] + g_bnB[f0 + 2], 0.f);
    float v3 = fmaxf(y.w * g_bnA[f0 + 3] + g_bnB[f0 + 3], 0.f);
    u32 h0, l0, h1, l1;
    bfsplit2(v0, v1, h0, l0);
    bfsplit2(v2, v3, h1, l1);
    *reinterpret_cast<u64*>(&g_Ah[(size_t)r * 320 + f0]) = (u64)h0 | ((u64)h1 << 32);
    *reinterpret_cast<u64*>(&g_Al[(size_t)r * 320 + f0]) = (u64)l0 | ((u64)l1 << 32);
}

__global__ void k_bnpool(const int* __restrict__ batch) {
    int gid = blockIdx.x * blockDim.x + threadIdx.x;
    if (gid >= NN * FF) return;
    int n = gid >> 6, f = gid & 63;
    float v = fmaxf(g_y[gid] * g_bnA[f] + g_bnB[f], 0.f);
    int b = batch[n];
    atomicAdd(&g_gsum[b * FF + f], v);
    if (f == 0) atomicAdd(&g_gcnt[b], 1);
}

__global__ void k_head(const float* __restrict__ W1, const float* __restrict__ b1,
                       const float* __restrict__ W2, const float* __restrict__ b2,
                       float* __restrict__ out) {
    int g = threadIdx.x;
    if (g >= GG) return;
    float cnt = fmaxf((float)g_gcnt[g], 1.0f);
    float inv = 1.0f / cnt;
    float gm[64];
#pragma unroll
    for (int k = 0; k < 64; k++) gm[k] = g_gsum[g * FF + k] * inv;
    float o = b2[0];
    for (int j = 0; j < 40; j++) {
        float s = b1[j];
#pragma unroll
        for (int k = 0; k < 64; k++) s = fmaf(gm[k], W1[k * 40 + j], s);
        o = fmaf(fmaxf(s, 0.f), W2[j], o);
    }
    out[g] = o;
}

// ---------------- launch ----------------
extern "C" void kernel_launch(void* const* d_in, const int* in_sizes, int n_in,
                              void* d_out, int out_size) {
    const float* x     = (const float*)d_in[0];
    const float* ea    = (const float*)d_in[1];
    const float* We    = (const float*)d_in[2];
    const float* be    = (const float*)d_in[3];
    const float* Wpre  = (const float*)d_in[4];
    const float* bpre  = (const float*)d_in[5];
    const float* Wpost = (const float*)d_in[6];
    const float* bpost = (const float*)d_in[7];
    const float* Wlin  = (const float*)d_in[8];
    const float* blin  = (const float*)d_in[9];
    const float* gamma = (const float*)d_in[10];
    const float* beta  = (const float*)d_in[11];
    const float* W1    = (const float*)d_in[12];
    const float* b1    = (const float*)d_in[13];
    const float* W2    = (const float*)d_in[14];
    const float* b2    = (const float*)d_in[15];
    const int*   ei    = (const int*)d_in[16];
    const int*   batch = (const int*)d_in[17];
    float* out = (float*)d_out;

    cudaFuncSetAttribute(k_pq_tc2, cudaFuncAttributeMaxDynamicSharedMemorySize, PQ2_SMEM);
    cudaFuncSetAttribute(k_gemm_tc2, cudaFuncAttributeMaxDynamicSharedMemorySize, GM2_SMEM);

    int gpq = (NN + 63) / 64;

    k_init<<<256, 256>>>();                              // idx 0
    k_cvtX<<<(NN * 16 + 255) / 256, 256>>>(x);           // idx 1
    k_cvtW<<<(128 * 64 + 255) / 256, 256>>>(Wpre);       // idx 2
    k_pq_tc2<<<gpq, 128, PQ2_SMEM>>>();                  // idx 3  <- PROFILED
    k_deg<<<(EE + 255) / 256, 256>>>(ei);                // idx 4
    k_scan1<<<SCB, 1024>>>();                            // idx 5
    k_scan3<<<SCB, 1024>>>();                            // idx 6
    k_scatter<<<(EE + 255) / 256, 256>>>(ei, ea);        // idx 7

    for (int l = 0; l < LL; l++) {
        k_prep<<<1, 256>>>(We + l * EDD * FF, be + l * FF, Wpre + l * 192 * FF, bpre + l * FF,
                           Wlin + l * FF * FF, bpost + l * FF, blin + l * FF);
        k_packB<<<(320 * 192 + 255) / 256, 256>>>(Wpost + l * 832 * FF, Wlin + l * FF * FF);
        if (l > 0) {
            k_cvtW<<<(128 * 64 + 255) / 256, 256>>>(Wpre + l * 192 * FF);
            k_pq_tc2<<<gpq, 128, PQ2_SMEM>>>();
        }
        k_agg<<<(NN + 7) / 8, 256>>>();
        k_gemm_tc2<<<gpq, 128, GM2_SMEM>>>();
        k_bnstat<<<(NN + 255) / 256, 256>>>();
        k_bnfin<<<1, 64>>>(gamma + l * FF, beta + l * FF);
        if (l == 0) k_bnapply<<<(NN * 16 + 255) / 256, 256>>>();
        else        k_bnpool<<<(NN * FF + 255) / 256, 256>>>(batch);
    }

    k_head<<<1, 64>>>(W1, b1, W2, b2, out);
}

// round 15
// speedup vs baseline: 1.1018x; 1.0262x over previous
#include <cuda_runtime.h>
#include <cuda_bf16.h>
#include <math.h>
#include <stddef.h>

#define NN 50000
#define EE 800000
#define FF 64
#define EDD 16
#define GG 64
#define LL 2
#define SCB ((NN + 1023) / 1024)

typedef unsigned long long u64;
typedef unsigned int u32;

// ---------------- packed f32x2 helpers ----------------
__device__ __forceinline__ u64 pk2(float x, float y) {
    u64 r; asm("mov.b64 %0,{%1,%2};" : "=l"(r) : "f"(x), "f"(y)); return r;
}
__device__ __forceinline__ float2 up2(u64 v) {
    float2 r; asm("mov.b64 {%0,%1},%2;" : "=f"(r.x), "=f"(r.y) : "l"(v)); return r;
}
__device__ __forceinline__ u64 ffma2(u64 a, u64 b, u64 c) {
    u64 d; asm("fma.rn.f32x2 %0,%1,%2,%3;" : "=l"(d) : "l"(a), "l"(b), "l"(c)); return d;
}
__device__ __forceinline__ u64 fadd2(u64 a, u64 b) {
    u64 d; asm("add.rn.f32x2 %0,%1,%2;" : "=l"(d) : "l"(a), "l"(b)); return d;
}

// ---------------- bf16 / mma / cp.async helpers ----------------
__device__ __forceinline__ void mma16816(float* d, const u32* a, const u32* b) {
    asm volatile("mma.sync.aligned.m16n8k16.row.col.f32.bf16.bf16.f32 "
                 "{%0,%1,%2,%3},{%4,%5,%6,%7},{%8,%9},{%0,%1,%2,%3};"
                 : "+f"(d[0]), "+f"(d[1]), "+f"(d[2]), "+f"(d[3])
                 : "r"(a[0]), "r"(a[1]), "r"(a[2]), "r"(a[3]), "r"(b[0]), "r"(b[1]));
}
__device__ __forceinline__ void bfsplit2(float a, float b, u32& hi, u32& lo) {
    __nv_bfloat16 ah = __float2bfloat16_rn(a);
    __nv_bfloat16 bh = __float2bfloat16_rn(b);
    __nv_bfloat16 al = __float2bfloat16_rn(a - __bfloat162float(ah));
    __nv_bfloat16 bl = __float2bfloat16_rn(b - __bfloat162float(bh));
    unsigned short ahs = *reinterpret_cast<unsigned short*>(&ah);
    unsigned short bhs = *reinterpret_cast<unsigned short*>(&bh);
    unsigned short als = *reinterpret_cast<unsigned short*>(&al);
    unsigned short bls = *reinterpret_cast<unsigned short*>(&bl);
    hi = (u32)ahs | ((u32)bhs << 16);
    lo = (u32)als | ((u32)bls << 16);
}
__device__ __forceinline__ u32 s2u(const void* p) {
    return (u32)__cvta_generic_to_shared(p);
}
__device__ __forceinline__ void cpa16(u32 dst, const void* src, int sz) {
    asm volatile("cp.async.cg.shared.global [%0],[%1],16,%2;" :: "r"(dst), "l"(src), "r"(sz));
}
#define CP_COMMIT asm volatile("cp.async.commit_group;")
#define CP_WAIT1  asm volatile("cp.async.wait_group 1;")
#define CP_WAIT0  asm volatile("cp.async.wait_group 0;")

// ---------------- scratch ----------------
__device__ int   g_deg[NN];
__device__ int   g_rowptr[NN + 1];
__device__ int   g_cursor[NN];
__device__ int   g_bsum[64];
__device__ int   g_csr_src[EE];
__device__ float g_eaperm[(size_t)EE * EDD];
__device__ float g_amp[NN];
__device__ float g_att[NN];
__device__ float g_logsum;
__device__ float g_P[NN * FF];
__device__ float g_Q[NN * FF];
__device__ float g_Wc[EDD * FF];
__device__ float g_hb[FF];
__device__ float g_bias2[FF];
__device__ float g_y[NN * FF];
__device__ float g_bnsum[FF];
__device__ float g_bnsq[FF];
__device__ float g_bnA[FF];
__device__ float g_bnB[FF];
__device__ float g_gsum[GG * FF];
__device__ int   g_gcnt[GG];
__device__ __nv_bfloat16 g_Ah[(size_t)NN * 320];
__device__ __nv_bfloat16 g_Al[(size_t)NN * 320];
__device__ __nv_bfloat16 g_Bth[192 * 320];
__device__ __nv_bfloat16 g_Btl[192 * 320];
__device__ __nv_bfloat16 g_Wth[128 * 64];
__device__ __nv_bfloat16 g_Wtl[128 * 64];

// ---------------- init / degree / CSR ----------------
__global__ void k_init() {
    int i  = blockIdx.x * blockDim.x + threadIdx.x;
    int nt = gridDim.x * blockDim.x;
    for (int j = i; j < NN; j += nt) { g_deg[j] = 0; g_cursor[j] = 0; }
    for (int j = i; j < GG * FF; j += nt) g_gsum[j] = 0.f;
    if (i < GG) g_gcnt[i] = 0;
    if (i < FF) { g_bnsum[i] = 0.f; g_bnsq[i] = 0.f; }
    if (i == 0) g_logsum = 0.f;
}

__global__ void k_deg(const int* __restrict__ ei) {
    int e = blockIdx.x * blockDim.x + threadIdx.x;
    if (e < EE) atomicAdd(&g_deg[ei[EE + e]], 1);
}

__global__ void k_scan1() {
    int tid = threadIdx.x, lane = tid & 31, wid = tid >> 5;
    int i = blockIdx.x * 1024 + tid;
    int v = (i < NN) ? g_deg[i] : 0;
    float lv = (i < NN) ? logf((float)v + 1.0f) : 0.0f;
#pragma unroll
    for (int off = 16; off > 0; off >>= 1) lv += __shfl_xor_sync(0xffffffffu, lv, off);
    if (lane == 0) atomicAdd(&g_logsum, lv);
    int x = v;
#pragma unroll
    for (int off = 1; off < 32; off <<= 1) {
        int t = __shfl_up_sync(0xffffffffu, x, off);
        if (lane >= off) x += t;
    }
    __shared__ int ws[32];
    if (lane == 31) ws[wid] = x;
    __syncthreads();
    if (wid == 0) {
        int s = ws[lane];
#pragma unroll
        for (int off = 1; off < 32; off <<= 1) {
            int t = __shfl_up_sync(0xffffffffu, s, off);
            if (lane >= off) s += t;
        }
        ws[lane] = s;
    }
    __syncthreads();
    int wbase = wid ? ws[wid - 1] : 0;
    if (i < NN) g_rowptr[i] = wbase + x - v;
    if (tid == 1023) g_bsum[blockIdx.x] = wbase + x;
}

__global__ void k_scan3() {
    __shared__ int sb[64];
    __shared__ int s_off, s_tot;
    int t = threadIdx.x;
    if (t < 64) sb[t] = (t < SCB) ? g_bsum[t] : 0;
    __syncthreads();
    if (t == 0) {
        int off = 0, tot = 0;
        for (int j = 0; j < SCB; j++) {
            if (j < (int)blockIdx.x) off += sb[j];
            tot += sb[j];
        }
        s_off = off; s_tot = tot;
    }
    __syncthreads();
    int i = blockIdx.x * 1024 + t;
    if (i < NN) {
        g_rowptr[i] += s_off;
        float avg = g_logsum / (float)NN;
        float d = (float)g_deg[i];
        float logd = logf(fmaxf(d, 1.0f) + 1.0f);
        g_amp[i] = logd / avg;
        g_att[i] = avg / logd;
    }
    if (blockIdx.x == gridDim.x - 1 && t == 0) g_rowptr[NN] = s_tot;
}

__global__ void k_scatter(const int* __restrict__ ei, const float* __restrict__ eattr) {
    int e = blockIdx.x * blockDim.x + threadIdx.x;
    if (e >= EE) return;
    int d = ei[EE + e];
    int pos = g_rowptr[d] + atomicAdd(&g_cursor[d], 1);
    g_csr_src[pos] = ei[e];
    const float4* srcp = reinterpret_cast<const float4*>(&eattr[(size_t)e * EDD]);
    float4* dstp = reinterpret_cast<float4*>(&g_eaperm[(size_t)pos * EDD]);
    dstp[0] = srcp[0];
    dstp[1] = srcp[1];
    dstp[2] = srcp[2];
    dstp[3] = srcp[3];
}

// ---------------- per-layer prep: Wc, hb, bias2 (BN zero handled elsewhere) ----------------
__global__ void k_prep(const float* __restrict__ We_l, const float* __restrict__ be_l,
                       const float* __restrict__ Wpre_l, const float* __restrict__ bpre_l,
                       const float* __restrict__ Wlin_l, const float* __restrict__ bpost_l,
                       const float* __restrict__ blin_l) {
    int tid = threadIdx.x;
    for (int idx = tid; idx < EDD * FF; idx += 256) {
        int j = idx / FF, f = idx % FF;
        float s = 0.f;
        for (int m = 0; m < FF; m++)
            s += We_l[j * FF + m] * Wpre_l[(128 + m) * FF + f];
        g_Wc[idx] = s;
    }
    if (tid < FF) {
        float s = bpre_l[tid];
        for (int m = 0; m < FF; m++)
            s += be_l[m] * Wpre_l[(128 + m) * FF + tid];
        g_hb[tid] = s;
        float b = blin_l[tid];
        for (int m = 0; m < FF; m++)
            b += bpost_l[m] * Wlin_l[m * 64 + tid];
        g_bias2[tid] = b;
    }
}

// ---- fused pack + Wlin-fold + bf16 split/transpose ----
__global__ void k_packB(const float* __restrict__ Wpost_l, const float* __restrict__ Wlin_l) {
    int idx = blockIdx.x * blockDim.x + threadIdx.x;
    if (idx >= 320 * 192) return;
    int k = idx / 192, c = idx % 192;
    int blk = c >> 6, cc = c & 63;
    float s = 0.f;
    if (k < 64) {
        if (blk == 0) {
            const float* wrow = &Wpost_l[k * 64];
#pragma unroll 8
            for (int m = 0; m < 64; m++)
                s += wrow[m] * __ldg(&Wlin_l[m * 64 + cc]);
        }
    } else {
        const float* wrow = &Wpost_l[(64 + blk * 256 + (k - 64)) * 64];
#pragma unroll 8
        for (int m = 0; m < 64; m++)
            s += wrow[m] * __ldg(&Wlin_l[m * 64 + cc]);
    }
    __nv_bfloat16 h = __float2bfloat16_rn(s);
    __nv_bfloat16 l = __float2bfloat16_rn(s - __bfloat162float(h));
    g_Bth[c * 320 + k] = h;
    g_Btl[c * 320 + k] = l;
}

__global__ void k_cvtW(const float* __restrict__ Wpre_l) {
    int idx = blockIdx.x * blockDim.x + threadIdx.x;
    if (idx >= 128 * 64) return;
    int c = idx >> 6, k = idx & 63;
    float v = (c < 64) ? Wpre_l[k * 64 + c] : Wpre_l[(64 + k) * 64 + (c - 64)];
    __nv_bfloat16 h = __float2bfloat16_rn(v);
    __nv_bfloat16 l = __float2bfloat16_rn(v - __bfloat162float(h));
    g_Wth[c * 64 + k] = h;
    g_Wtl[c * 64 + k] = l;
}

__global__ void k_cvtX(const float* __restrict__ X) {
    int gid = blockIdx.x * blockDim.x + threadIdx.x;
    if (gid >= NN * 16) return;
    int r = gid >> 4, q = gid & 15;
    float4 v = *reinterpret_cast<const float4*>(&X[(size_t)r * 64 + q * 4]);
    u32 h0, l0, h1, l1;
    bfsplit2(v.x, v.y, h0, l0);
    bfsplit2(v.z, v.w, h1, l1);
    *reinterpret_cast<u64*>(&g_Ah[(size_t)r * 320 + q * 4]) = (u64)h0 | ((u64)h1 << 32);
    *reinterpret_cast<u64*>(&g_Al[(size_t)r * 320 + q * 4]) = (u64)l0 | ((u64)l1 << 32);
}

// ================= pipelined TC GEMM machinery =================
#define PITCH 40

__device__ __forceinline__ void stageA(__nv_bfloat16* sAh, __nv_bfloat16* sAl,
                                       int row0, int kc, int tid) {
#pragma unroll
    for (int it = 0; it < 2; it++) {
        int idx = tid + it * 128;
        int r = idx >> 2, q = idx & 3;
        int n = row0 + r;
        int nc = (n < NN) ? n : (NN - 1);
        int sz = (n < NN) ? 16 : 0;
        cpa16(s2u(sAh + r * PITCH + q * 8), &g_Ah[(size_t)nc * 320 + kc + q * 8], sz);
        cpa16(s2u(sAl + r * PITCH + q * 8), &g_Al[(size_t)nc * 320 + kc + q * 8], sz);
    }
}
__device__ __forceinline__ void stageB192(__nv_bfloat16* sBh, __nv_bfloat16* sBl,
                                          int kc, int tid) {
#pragma unroll
    for (int it = 0; it < 6; it++) {
        int idx = tid + it * 128;
        int r = idx >> 2, q = idx & 3;
        cpa16(s2u(sBh + r * PITCH + q * 8), &g_Bth[(size_t)r * 320 + kc + q * 8], 16);
        cpa16(s2u(sBl + r * PITCH + q * 8), &g_Btl[(size_t)r * 320 + kc + q * 8], 16);
    }
}
__device__ __forceinline__ void stageB128(__nv_bfloat16* sBh, __nv_bfloat16* sBl,
                                          int kc, int tid) {
#pragma unroll
    for (int it = 0; it < 4; it++) {
        int idx = tid + it * 128;
        int r = idx >> 2, q = idx & 3;
        cpa16(s2u(sBh + r * PITCH + q * 8), &g_Wth[r * 64 + kc + q * 8], 16);
        cpa16(s2u(sBl + r * PITCH + q * 8), &g_Wtl[r * 64 + kc + q * 8], 16);
    }
}

template<int NJ>
__device__ __forceinline__ void tcchunkN(const __nv_bfloat16* sAh, const __nv_bfloat16* sAl,
                                         const __nv_bfloat16* sBh, const __nv_bfloat16* sBl,
                                         int m0, int n0l, int g, int t, float acc[][NJ][4]) {
#pragma unroll
    for (int kk = 0; kk < 32; kk += 16) {
        u32 ah[2][4], al[2][4];
#pragma unroll
        for (int mi = 0; mi < 2; mi++) {
            int r = m0 + mi * 16 + g;
            int cA = kk + 2 * t;
            ah[mi][0] = *reinterpret_cast<const u32*>(&sAh[r * PITCH + cA]);
            ah[mi][1] = *reinterpret_cast<const u32*>(&sAh[(r + 8) * PITCH + cA]);
            ah[mi][2] = *reinterpret_cast<const u32*>(&sAh[r * PITCH + cA + 8]);
            ah[mi][3] = *reinterpret_cast<const u32*>(&sAh[(r + 8) * PITCH + cA + 8]);
            al[mi][0] = *reinterpret_cast<const u32*>(&sAl[r * PITCH + cA]);
            al[mi][1] = *reinterpret_cast<const u32*>(&sAl[(r + 8) * PITCH + cA]);
            al[mi][2] = *reinterpret_cast<const u32*>(&sAl[r * PITCH + cA + 8]);
            al[mi][3] = *reinterpret_cast<const u32*>(&sAl[(r + 8) * PITCH + cA + 8]);
        }
#pragma unroll
        for (int j = 0; j < NJ; j++) {
            int nr = n0l + 8 * j + g;
            int cB = kk + 2 * t;
            u32 bh[2], bl[2];
            bh[0] = *reinterpret_cast<const u32*>(&sBh[nr * PITCH + cB]);
            bh[1] = *reinterpret_cast<const u32*>(&sBh[nr * PITCH + cB + 8]);
            bl[0] = *reinterpret_cast<const u32*>(&sBl[nr * PITCH + cB]);
            bl[1] = *reinterpret_cast<const u32*>(&sBl[nr * PITCH + cB + 8]);
#pragma unroll
            for (int mi = 0; mi < 2; mi++) {
                mma16816(acc[mi][j], ah[mi], bh);
                mma16816(acc[mi][j], ah[mi], bl);
                mma16816(acc[mi][j], al[mi], bh);
            }
        }
    }
}

// ---- fused main GEMM + combine: y[N,64] ; grid 782, 128 thr, dyn smem ----
__global__ void __launch_bounds__(128) k_gemm_tc2() {
    extern __shared__ __nv_bfloat16 dsm[];
    __nv_bfloat16* sAh[2] = {dsm, dsm + 64 * PITCH};
    __nv_bfloat16* sAl[2] = {dsm + 2 * 64 * PITCH, dsm + 3 * 64 * PITCH};
    __nv_bfloat16* base = dsm + 4 * 64 * PITCH;
    __nv_bfloat16* sBh[2] = {base, base + 192 * PITCH};
    __nv_bfloat16* sBl[2] = {base + 2 * 192 * PITCH, base + 3 * 192 * PITCH};
    int tid = threadIdx.x;
    int warp = tid >> 5, lane = tid & 31;
    int g = lane >> 2, t = lane & 3;
    int wm = warp >> 1, wn = warp & 1;
    int m0 = wm * 32, n0l = wn * 32;
    int row0 = blockIdx.x * 64;
    float acc[3][2][4][4];
#pragma unroll
    for (int cb = 0; cb < 3; cb++)
#pragma unroll
        for (int mi = 0; mi < 2; mi++)
#pragma unroll
            for (int j = 0; j < 4; j++)
#pragma unroll
                for (int q = 0; q < 4; q++) acc[cb][mi][j][q] = 0.f;

    stageA(sAh[0], sAl[0], row0, 0, tid);
    stageB192(sBh[0], sBl[0], 0, tid);
    CP_COMMIT;
    for (int i = 0; i < 10; i++) {
        int s = i & 1;
        if (i + 1 < 10) {
            stageA(sAh[s ^ 1], sAl[s ^ 1], row0, (i + 1) * 32, tid);
            stageB192(sBh[s ^ 1], sBl[s ^ 1], (i + 1) * 32, tid);
            CP_COMMIT;
            CP_WAIT1;
        } else {
            CP_WAIT0;
        }
        __syncthreads();
#pragma unroll
        for (int cb = 0; cb < 3; cb++)
            tcchunkN<4>(sAh[s], sAl[s], sBh[s] + cb * 64 * PITCH, sBl[s] + cb * 64 * PITCH,
                        m0, n0l, g, t, acc[cb]);
        __syncthreads();
    }
#pragma unroll
    for (int mi = 0; mi < 2; mi++) {
        int r0 = row0 + m0 + mi * 16 + g;
        int r1 = r0 + 8;
        float amp0 = (r0 < NN) ? g_amp[r0] : 0.f;
        float att0 = (r0 < NN) ? g_att[r0] : 0.f;
        float amp1 = (r1 < NN) ? g_amp[r1] : 0.f;
        float att1 = (r1 < NN) ? g_att[r1] : 0.f;
#pragma unroll
        for (int j = 0; j < 4; j++) {
            int c = n0l + 8 * j + 2 * t;
            float b0 = g_bias2[c], b1 = g_bias2[c + 1];
            if (r0 < NN) {
                float y0 = acc[0][mi][j][0] + amp0 * acc[1][mi][j][0] + att0 * acc[2][mi][j][0] + b0;
                float y1 = acc[0][mi][j][1] + amp0 * acc[1][mi][j][1] + att0 * acc[2][mi][j][1] + b1;
                *reinterpret_cast<float2*>(&g_y[(size_t)r0 * 64 + c]) = make_float2(y0, y1);
            }
            if (r1 < NN) {
                float y2 = acc[0][mi][j][2] + amp1 * acc[1][mi][j][2] + att1 * acc[2][mi][j][2] + b0;
                float y3 = acc[0][mi][j][3] + amp1 * acc[1][mi][j][3] + att1 * acc[2][mi][j][3] + b1;
                *reinterpret_cast<float2*>(&g_y[(size_t)r1 * 64 + c]) = make_float2(y2, y3);
            }
        }
    }
}
#define GM2_SMEM ((4 * 64 + 4 * 192) * PITCH * 2)   // 81920 bytes

// ---- fused PQ GEMM: [P|Q][N,128] = X @ Wt ; grid 782, 128 thr, dyn smem ----
__global__ void __launch_bounds__(128) k_pq_tc2() {
    extern __shared__ __nv_bfloat16 dsm[];
    __nv_bfloat16* sAh[2] = {dsm, dsm + 64 * PITCH};
    __nv_bfloat16* sAl[2] = {dsm + 2 * 64 * PITCH, dsm + 3 * 64 * PITCH};
    __nv_bfloat16* base = dsm + 4 * 64 * PITCH;
    __nv_bfloat16* sBh[2] = {base, base + 128 * PITCH};
    __nv_bfloat16* sBl[2] = {base + 2 * 128 * PITCH, base + 3 * 128 * PITCH};
    int tid = threadIdx.x;
    int warp = tid >> 5, lane = tid & 31;
    int g = lane >> 2, t = lane & 3;
    int wm = warp >> 1, wn = warp & 1;
    int m0 = wm * 32, n0l = wn * 64;
    int row0 = blockIdx.x * 64;
    float acc[2][8][4];
#pragma unroll
    for (int mi = 0; mi < 2; mi++)
#pragma unroll
        for (int j = 0; j < 8; j++)
#pragma unroll
            for (int q = 0; q < 4; q++) acc[mi][j][q] = 0.f;

    stageA(sAh[0], sAl[0], row0, 0, tid);
    stageB128(sBh[0], sBl[0], 0, tid);
    CP_COMMIT;
#pragma unroll
    for (int i = 0; i < 2; i++) {
        int s = i & 1;
        if (i + 1 < 2) {
            stageA(sAh[1], sAl[1], row0, 32, tid);
            stageB128(sBh[1], sBl[1], 32, tid);
            CP_COMMIT;
            CP_WAIT1;
        } else {
            CP_WAIT0;
        }
        __syncthreads();
        tcchunkN<8>(sAh[s], sAl[s], sBh[s], sBl[s], m0, n0l, g, t, acc);
        __syncthreads();
    }
    float* dst = (wn == 0) ? g_P : g_Q;
#pragma unroll
    for (int mi = 0; mi < 2; mi++) {
#pragma unroll
        for (int j = 0; j < 8; j++) {
            int r = row0 + m0 + mi * 16 + g;
            int c = 8 * j + 2 * t;
            if (r < NN)
                *reinterpret_cast<float2*>(&dst[(size_t)r * 64 + c]) =
                    make_float2(acc[mi][j][0], acc[mi][j][1]);
            if (r + 8 < NN)
                *reinterpret_cast<float2*>(&dst[(size_t)(r + 8) * 64 + c]) =
                    make_float2(acc[mi][j][2], acc[mi][j][3]);
        }
    }
}
#define PQ2_SMEM ((4 * 64 + 4 * 128) * PITCH * 2)   // 61440 bytes

// ---------------- per-node aggregation (R12 depth-1 form) ----------------
__global__ void __launch_bounds__(256) k_agg() {
    int warp = (blockIdx.x * blockDim.x + threadIdx.x) >> 5;
    int lane = threadIdx.x & 31;
    if (warp >= NN) return;
    int n = warp;
    int fp = 2 * lane;
    u64 wc2[16];
#pragma unroll
    for (int k = 0; k < 16; k++) wc2[k] = *reinterpret_cast<const u64*>(&g_Wc[k * 64 + fp]);
    u64 base2 = fadd2(*reinterpret_cast<const u64*>(&g_P[(size_t)n * FF + fp]),
                      *reinterpret_cast<const u64*>(&g_hb[fp]));
    int s = g_rowptr[n], e = g_rowptr[n + 1];
    u64 sum2 = 0ull, sq2 = 0ull;
    float mn0 = 3.4e38f, mn1 = 3.4e38f, mx0 = -3.4e38f, mx1 = -3.4e38f;
    int src_n = 0; u64 q_n = 0ull;
    if (s < e) {
        src_n = g_csr_src[s];
        q_n = *reinterpret_cast<const u64*>(&g_Q[(size_t)src_n * FF + fp]);
    }
    for (int i = s; i < e; i++) {
        u64 qv = q_n;
        if (i + 1 < e) {
            src_n = g_csr_src[i + 1];
            q_n = *reinterpret_cast<const u64*>(&g_Q[(size_t)src_n * FF + fp]);
        }
        const float* ep = &g_eaperm[(size_t)i * EDD];
        float eav[16];
#pragma unroll
        for (int k = 0; k < 16; k += 4) {
            float4 v = *reinterpret_cast<const float4*>(ep + k);
            eav[k] = v.x; eav[k + 1] = v.y; eav[k + 2] = v.z; eav[k + 3] = v.w;
        }
        u64 hA = fadd2(base2, qv);
        u64 p0 = 0ull, p1 = 0ull;
#pragma unroll
        for (int k = 0; k < 8; k++) {
            p0 = ffma2(pk2(eav[2 * k], eav[2 * k]), wc2[2 * k], p0);
            p1 = ffma2(pk2(eav[2 * k + 1], eav[2 * k + 1]), wc2[2 * k + 1], p1);
        }
        u64 h2 = fadd2(hA, fadd2(p0, p1));
        sum2 = fadd2(sum2, h2);
        sq2 = ffma2(h2, h2, sq2);
        float2 h = up2(h2);
        mn0 = fminf(mn0, h.x); mx0 = fmaxf(mx0, h.x);
        mn1 = fminf(mn1, h.y); mx1 = fmaxf(mx1, h.y);
    }
    float deg = (float)(e - s);
    float degc = fmaxf(deg, 1.0f);
    float2 sum = up2(sum2), sq = up2(sq2);
    float mean0 = sum.x / degc, mean1 = sum.y / degc;
    float std0 = sqrtf(fmaxf(sq.x / degc - mean0 * mean0, 0.f) + 1e-5f);
    float std1 = sqrtf(fmaxf(sq.y / degc - mean1 * mean1, 0.f) + 1e-5f);
    if (deg == 0.f) { mn0 = 0.f; mx0 = 0.f; mn1 = 0.f; mx1 = 0.f; }
    __nv_bfloat16* ah = &g_Ah[(size_t)n * 320 + 64 + fp];
    __nv_bfloat16* al = &g_Al[(size_t)n * 320 + 64 + fp];
    u32 hi, lo;
    bfsplit2(mean0, mean1, hi, lo);
    *reinterpret_cast<u32*>(ah + 0)   = hi; *reinterpret_cast<u32*>(al + 0)   = lo;
    bfsplit2(mn0, mn1, hi, lo);
    *reinterpret_cast<u32*>(ah + 64)  = hi; *reinterpret_cast<u32*>(al + 64)  = lo;
    bfsplit2(mx0, mx1, hi, lo);
    *reinterpret_cast<u32*>(ah + 128) = hi; *reinterpret_cast<u32*>(al + 128) = lo;
    bfsplit2(std0, std1, hi, lo);
    *reinterpret_cast<u32*>(ah + 192) = hi; *reinterpret_cast<u32*>(al + 192) = lo;
}

// ---------------- BN stats over y ----------------
__global__ void __launch_bounds__(256) k_bnstat() {
    int f = threadIdx.x & 63;
    int g = threadIdx.x >> 6;
    __shared__ float sred[256];
    float ys = 0.f, yq = 0.f;
    int n0 = blockIdx.x * 256;
    for (int it = 0; it < 64; it++) {
        int n = n0 + it * 4 + g;
        if (n < NN) {
            float y = g_y[(size_t)n * FF + f];
            ys += y;
            yq = fmaf(y, y, yq);
        }
    }
    sred[threadIdx.x] = ys;
    __syncthreads();
    if (threadIdx.x < 64) {
        float s = sred[f] + sred[64 + f] + sred[128 + f] + sred[192 + f];
        atomicAdd(&g_bnsum[f], s);
    }
    __syncthreads();
    sred[threadIdx.x] = yq;
    __syncthreads();
    if (threadIdx.x < 64) {
        float s = sred[f] + sred[64 + f] + sred[128 + f] + sred[192 + f];
        atomicAdd(&g_bnsq[f], s);
    }
}

// compute bnA/bnB, then self-reset accumulators for the next layer
__global__ void k_bnfin(const float* __restrict__ gamma_l, const float* __restrict__ beta_l) {
    int f = threadIdx.x;
    if (f >= FF) return;
    float mu = g_bnsum[f] / (float)NN;
    float var = g_bnsq[f] / (float)NN - mu * mu;
    float rs = rsqrtf(var + 1e-5f);
    float a = rs * gamma_l[f];
    g_bnA[f] = a;
    g_bnB[f] = beta_l[f] - mu * a;
    g_bnsum[f] = 0.f;
    g_bnsq[f] = 0.f;
}

__global__ void k_bnapply() {
    int gid = blockIdx.x * blockDim.x + threadIdx.x;
    if (gid >= NN * 16) return;
    int r = gid >> 4, q = gid & 15;
    int f0 = q * 4;
    float4 y = *reinterpret_cast<const float4*>(&g_y[(size_t)r * 64 + f0]);
    float v0 = fmaxf(y.x * g_bnA[f0 + 0] + g_bnB[f0 + 0], 0.f);
    float v1 = fmaxf(y.y * g_bnA[f0 + 1] + g_bnB[f0 + 1], 0.f);
    float v2 = fmaxf(y.z * g_bnA[f0 + 2] + g_bnB[f0 + 2], 0.f);
    float v3 = fmaxf(y.w * g_bnA[f0 + 3] + g_bnB[f0 + 3], 0.f);
    u32 h0, l0, h1, l1;
    bfsplit2(v0, v1, h0, l0);
    bfsplit2(v2, v3, h1, l1);
    *reinterpret_cast<u64*>(&g_Ah[(size_t)r * 320 + f0]) = (u64)h0 | ((u64)h1 << 32);
    *reinterpret_cast<u64*>(&g_Al[(size_t)r * 320 + f0]) = (u64)l0 | ((u64)l1 << 32);
}

__global__ void k_bnpool(const int* __restrict__ batch) {
    int gid = blockIdx.x * blockDim.x + threadIdx.x;
    if (gid >= NN * FF) return;
    int n = gid >> 6, f = gid & 63;
    float v = fmaxf(g_y[gid] * g_bnA[f] + g_bnB[f], 0.f);
    int b = batch[n];
    atomicAdd(&g_gsum[b * FF + f], v);
    if (f == 0) atomicAdd(&g_gcnt[b], 1);
}

__global__ void k_head(const float* __restrict__ W1, const float* __restrict__ b1,
                       const float* __restrict__ W2, const float* __restrict__ b2,
                       float* __restrict__ out) {
    int g = threadIdx.x;
    if (g >= GG) return;
    float cnt = fmaxf((float)g_gcnt[g], 1.0f);
    float inv = 1.0f / cnt;
    float gm[64];
#pragma unroll
    for (int k = 0; k < 64; k++) gm[k] = g_gsum[g * FF + k] * inv;
    float o = b2[0];
    for (int j = 0; j < 40; j++) {
        float s = b1[j];
#pragma unroll
        for (int k = 0; k < 64; k++) s = fmaf(gm[k], W1[k * 40 + j], s);
        o = fmaf(fmaxf(s, 0.f), W2[j], o);
    }
    out[g] = o;
}

// ---------------- launch (fork/join streams inside graph capture) ----------------
extern "C" void kernel_launch(void* const* d_in, const int* in_sizes, int n_in,
                              void* d_out, int out_size) {
    const float* x     = (const float*)d_in[0];
    const float* ea    = (const float*)d_in[1];
    const float* We    = (const float*)d_in[2];
    const float* be    = (const float*)d_in[3];
    const float* Wpre  = (const float*)d_in[4];
    const float* bpre  = (const float*)d_in[5];
    const float* Wpost = (const float*)d_in[6];
    const float* bpost = (const float*)d_in[7];
    const float* Wlin  = (const float*)d_in[8];
    const float* blin  = (const float*)d_in[9];
    const float* gamma = (const float*)d_in[10];
    const float* beta  = (const float*)d_in[11];
    const float* W1    = (const float*)d_in[12];
    const float* b1    = (const float*)d_in[13];
    const float* W2    = (const float*)d_in[14];
    const float* b2    = (const float*)d_in[15];
    const int*   ei    = (const int*)d_in[16];
    const int*   batch = (const int*)d_in[17];
    float* out = (float*)d_out;

    static cudaStream_t s1 = nullptr;
    static cudaEvent_t evA = nullptr, evB = nullptr, evC = nullptr, evD = nullptr;
    if (!s1) {
        cudaStreamCreate(&s1);
        cudaEventCreateWithFlags(&evA, cudaEventDisableTiming);
        cudaEventCreateWithFlags(&evB, cudaEventDisableTiming);
        cudaEventCreateWithFlags(&evC, cudaEventDisableTiming);
        cudaEventCreateWithFlags(&evD, cudaEventDisableTiming);
        cudaFuncSetAttribute(k_pq_tc2, cudaFuncAttributeMaxDynamicSharedMemorySize, PQ2_SMEM);
        cudaFuncSetAttribute(k_gemm_tc2, cudaFuncAttributeMaxDynamicSharedMemorySize, GM2_SMEM);
    }

    int gpq = (NN + 63) / 64;

    // fork: side chain B on s1
    cudaEventRecord(evA, 0);
    cudaStreamWaitEvent(s1, evA, 0);

    // chain A (s0): CSR build
    k_init<<<256, 256>>>();
    k_deg<<<(EE + 255) / 256, 256>>>(ei);
    k_scan1<<<SCB, 1024>>>();
    k_scan3<<<SCB, 1024>>>();
    k_scatter<<<(EE + 255) / 256, 256>>>(ei, ea);

    // chain B (s1): node/weight side, layer 0
    k_cvtX<<<(NN * 16 + 255) / 256, 256, 0, s1>>>(x);
    k_cvtW<<<(128 * 64 + 255) / 256, 256, 0, s1>>>(Wpre);
    k_pq_tc2<<<gpq, 128, PQ2_SMEM, s1>>>();
    k_prep<<<1, 256, 0, s1>>>(We, be, Wpre, bpre, Wlin, bpost, blin);
    k_packB<<<(320 * 192 + 255) / 256, 256, 0, s1>>>(Wpost, Wlin);

    // join
    cudaEventRecord(evB, s1);
    cudaStreamWaitEvent(0, evB, 0);

    // ---- layer 0 ----
    k_agg<<<(NN + 7) / 8, 256>>>();
    k_gemm_tc2<<<gpq, 128, GM2_SMEM>>>();

    // fork: layer-1 weight prep on s1 while BN chain runs on s0
    cudaEventRecord(evC, 0);
    cudaStreamWaitEvent(s1, evC, 0);
    k_prep<<<1, 256, 0, s1>>>(We + EDD * FF, be + FF, Wpre + 192 * FF, bpre + FF,
                              Wlin + FF * FF, bpost + FF, blin + FF);
    k_packB<<<(320 * 192 + 255) / 256, 256, 0, s1>>>(Wpost + 832 * FF, Wlin + FF * FF);
    k_cvtW<<<(128 * 64 + 255) / 256, 256, 0, s1>>>(Wpre + 192 * FF);

    k_bnstat<<<(NN + 255) / 256, 256>>>();
    k_bnfin<<<1, 64>>>(gamma, beta);
    k_bnapply<<<(NN * 16 + 255) / 256, 256>>>();

    // join
    cudaEventRecord(evD, s1);
    cudaStreamWaitEvent(0, evD, 0);

    // ---- layer 1 ----
    k_pq_tc2<<<gpq, 128, PQ2_SMEM>>>();
    k_agg<<<(NN + 7) / 8, 256>>>();
    k_gemm_tc2<<<gpq, 128, GM2_SMEM>>>();
    k_bnstat<<<(NN + 255) / 256, 256>>>();
    k_bnfin<<<1, 64>>>(gamma + FF, beta + FF);
    k_bnpool<<<(NN * FF + 255) / 256, 256>>>(batch);

    k_head<<<1, 64>>>(W1, b1, W2, b2, out);
}

// round 16
// speedup vs baseline: 1.1224x; 1.0187x over previous
#include <cuda_runtime.h>
#include <cuda_bf16.h>
#include <math.h>
#include <stddef.h>

#define NN 50000
#define EE 800000
#define FF 64
#define EDD 16
#define GG 64
#define LL 2
#define SCB ((NN + 1023) / 1024)

typedef unsigned long long u64;
typedef unsigned int u32;

// ---------------- packed f32x2 helpers ----------------
__device__ __forceinline__ u64 pk2(float x, float y) {
    u64 r; asm("mov.b64 %0,{%1,%2};" : "=l"(r) : "f"(x), "f"(y)); return r;
}
__device__ __forceinline__ float2 up2(u64 v) {
    float2 r; asm("mov.b64 {%0,%1},%2;" : "=f"(r.x), "=f"(r.y) : "l"(v)); return r;
}
__device__ __forceinline__ u64 ffma2(u64 a, u64 b, u64 c) {
    u64 d; asm("fma.rn.f32x2 %0,%1,%2,%3;" : "=l"(d) : "l"(a), "l"(b), "l"(c)); return d;
}
__device__ __forceinline__ u64 fadd2(u64 a, u64 b) {
    u64 d; asm("add.rn.f32x2 %0,%1,%2;" : "=l"(d) : "l"(a), "l"(b)); return d;
}

// ---------------- bf16 / mma / cp.async helpers ----------------
__device__ __forceinline__ void mma16816(float* d, const u32* a, const u32* b) {
    asm volatile("mma.sync.aligned.m16n8k16.row.col.f32.bf16.bf16.f32 "
                 "{%0,%1,%2,%3},{%4,%5,%6,%7},{%8,%9},{%0,%1,%2,%3};"
                 : "+f"(d[0]), "+f"(d[1]), "+f"(d[2]), "+f"(d[3])
                 : "r"(a[0]), "r"(a[1]), "r"(a[2]), "r"(a[3]), "r"(b[0]), "r"(b[1]));
}
__device__ __forceinline__ void bfsplit2(float a, float b, u32& hi, u32& lo) {
    __nv_bfloat16 ah = __float2bfloat16_rn(a);
    __nv_bfloat16 bh = __float2bfloat16_rn(b);
    __nv_bfloat16 al = __float2bfloat16_rn(a - __bfloat162float(ah));
    __nv_bfloat16 bl = __float2bfloat16_rn(b - __bfloat162float(bh));
    unsigned short ahs = *reinterpret_cast<unsigned short*>(&ah);
    unsigned short bhs = *reinterpret_cast<unsigned short*>(&bh);
    unsigned short als = *reinterpret_cast<unsigned short*>(&al);
    unsigned short bls = *reinterpret_cast<unsigned short*>(&bl);
    hi = (u32)ahs | ((u32)bhs << 16);
    lo = (u32)als | ((u32)bls << 16);
}
__device__ __forceinline__ u32 s2u(const void* p) {
    return (u32)__cvta_generic_to_shared(p);
}
__device__ __forceinline__ void cpa16(u32 dst, const void* src, int sz) {
    asm volatile("cp.async.cg.shared.global [%0],[%1],16,%2;" :: "r"(dst), "l"(src), "r"(sz));
}
#define CP_COMMIT asm volatile("cp.async.commit_group;")
#define CP_WAIT1  asm volatile("cp.async.wait_group 1;")
#define CP_WAIT0  asm volatile("cp.async.wait_group 0;")

// ---------------- scratch ----------------
__device__ int   g_deg[NN];
__device__ int   g_rowptr[NN + 1];
__device__ int   g_cursor[NN];
__device__ int   g_bsum[64];
__device__ int   g_csr_src[EE];
__device__ float g_eaperm[(size_t)EE * EDD];
__device__ float g_amp[NN];
__device__ float g_att[NN];
__device__ float g_logsum;
__device__ float g_P[NN * FF];
__device__ float g_Q[NN * FF];
__device__ float g_Wc[EDD * FF];
__device__ float g_hb[FF];
__device__ float g_bias2[FF];
__device__ float g_y[NN * FF];
__device__ float g_bnsum[FF];
__device__ float g_bnsq[FF];
__device__ float g_bnA[FF];
__device__ float g_bnB[FF];
__device__ float g_gsum[GG * FF];
__device__ int   g_gcnt[GG];
__device__ __nv_bfloat16 g_Ah[(size_t)NN * 320];
__device__ __nv_bfloat16 g_Al[(size_t)NN * 320];
__device__ __nv_bfloat16 g_Bth[192 * 320];
__device__ __nv_bfloat16 g_Btl[192 * 320];
__device__ __nv_bfloat16 g_Wth[128 * 64];
__device__ __nv_bfloat16 g_Wtl[128 * 64];

// ---------------- init / degree / CSR ----------------
__global__ void k_init() {
    int i  = blockIdx.x * blockDim.x + threadIdx.x;
    int nt = gridDim.x * blockDim.x;
    for (int j = i; j < NN; j += nt) { g_deg[j] = 0; g_cursor[j] = 0; }
    for (int j = i; j < GG * FF; j += nt) g_gsum[j] = 0.f;
    if (i < GG) g_gcnt[i] = 0;
    if (i < FF) { g_bnsum[i] = 0.f; g_bnsq[i] = 0.f; }
    if (i == 0) g_logsum = 0.f;
}

__global__ void k_deg(const int* __restrict__ ei) {
    int e = blockIdx.x * blockDim.x + threadIdx.x;
    if (e < EE) atomicAdd(&g_deg[ei[EE + e]], 1);
}

__global__ void k_scan1() {
    int tid = threadIdx.x, lane = tid & 31, wid = tid >> 5;
    int i = blockIdx.x * 1024 + tid;
    int v = (i < NN) ? g_deg[i] : 0;
    float lv = (i < NN) ? logf((float)v + 1.0f) : 0.0f;
#pragma unroll
    for (int off = 16; off > 0; off >>= 1) lv += __shfl_xor_sync(0xffffffffu, lv, off);
    if (lane == 0) atomicAdd(&g_logsum, lv);
    int x = v;
#pragma unroll
    for (int off = 1; off < 32; off <<= 1) {
        int t = __shfl_up_sync(0xffffffffu, x, off);
        if (lane >= off) x += t;
    }
    __shared__ int ws[32];
    if (lane == 31) ws[wid] = x;
    __syncthreads();
    if (wid == 0) {
        int s = ws[lane];
#pragma unroll
        for (int off = 1; off < 32; off <<= 1) {
            int t = __shfl_up_sync(0xffffffffu, s, off);
            if (lane >= off) s += t;
        }
        ws[lane] = s;
    }
    __syncthreads();
    int wbase = wid ? ws[wid - 1] : 0;
    if (i < NN) g_rowptr[i] = wbase + x - v;
    if (tid == 1023) g_bsum[blockIdx.x] = wbase + x;
}

__global__ void k_scan3() {
    __shared__ int sb[64];
    __shared__ int s_off, s_tot;
    int t = threadIdx.x;
    if (t < 64) sb[t] = (t < SCB) ? g_bsum[t] : 0;
    __syncthreads();
    if (t == 0) {
        int off = 0, tot = 0;
        for (int j = 0; j < SCB; j++) {
            if (j < (int)blockIdx.x) off += sb[j];
            tot += sb[j];
        }
        s_off = off; s_tot = tot;
    }
    __syncthreads();
    int i = blockIdx.x * 1024 + t;
    if (i < NN) {
        g_rowptr[i] += s_off;
        float avg = g_logsum / (float)NN;
        float d = (float)g_deg[i];
        float logd = logf(fmaxf(d, 1.0f) + 1.0f);
        g_amp[i] = logd / avg;
        g_att[i] = avg / logd;
    }
    if (blockIdx.x == gridDim.x - 1 && t == 0) g_rowptr[NN] = s_tot;
}

__global__ void k_scatter(const int* __restrict__ ei, const float* __restrict__ eattr) {
    int e = blockIdx.x * blockDim.x + threadIdx.x;
    if (e >= EE) return;
    int d = ei[EE + e];
    int pos = g_rowptr[d] + atomicAdd(&g_cursor[d], 1);
    g_csr_src[pos] = ei[e];
    const float4* srcp = reinterpret_cast<const float4*>(&eattr[(size_t)e * EDD]);
    float4* dstp = reinterpret_cast<float4*>(&g_eaperm[(size_t)pos * EDD]);
    dstp[0] = srcp[0];
    dstp[1] = srcp[1];
    dstp[2] = srcp[2];
    dstp[3] = srcp[3];
}

// ---------------- per-layer prep ----------------
__global__ void k_prep(const float* __restrict__ We_l, const float* __restrict__ be_l,
                       const float* __restrict__ Wpre_l, const float* __restrict__ bpre_l,
                       const float* __restrict__ Wlin_l, const float* __restrict__ bpost_l,
                       const float* __restrict__ blin_l) {
    int tid = threadIdx.x;
    for (int idx = tid; idx < EDD * FF; idx += 256) {
        int j = idx / FF, f = idx % FF;
        float s = 0.f;
        for (int m = 0; m < FF; m++)
            s += We_l[j * FF + m] * Wpre_l[(128 + m) * FF + f];
        g_Wc[idx] = s;
    }
    if (tid < FF) {
        float s = bpre_l[tid];
        for (int m = 0; m < FF; m++)
            s += be_l[m] * Wpre_l[(128 + m) * FF + tid];
        g_hb[tid] = s;
        float b = blin_l[tid];
        for (int m = 0; m < FF; m++)
            b += bpost_l[m] * Wlin_l[m * 64 + tid];
        g_bias2[tid] = b;
    }
}

__global__ void k_packB(const float* __restrict__ Wpost_l, const float* __restrict__ Wlin_l) {
    int idx = blockIdx.x * blockDim.x + threadIdx.x;
    if (idx >= 320 * 192) return;
    int k = idx / 192, c = idx % 192;
    int blk = c >> 6, cc = c & 63;
    float s = 0.f;
    if (k < 64) {
        if (blk == 0) {
            const float* wrow = &Wpost_l[k * 64];
#pragma unroll 8
            for (int m = 0; m < 64; m++)
                s += wrow[m] * __ldg(&Wlin_l[m * 64 + cc]);
        }
    } else {
        const float* wrow = &Wpost_l[(64 + blk * 256 + (k - 64)) * 64];
#pragma unroll 8
        for (int m = 0; m < 64; m++)
            s += wrow[m] * __ldg(&Wlin_l[m * 64 + cc]);
    }
    __nv_bfloat16 h = __float2bfloat16_rn(s);
    __nv_bfloat16 l = __float2bfloat16_rn(s - __bfloat162float(h));
    g_Bth[c * 320 + k] = h;
    g_Btl[c * 320 + k] = l;
}

__global__ void k_cvtW(const float* __restrict__ Wpre_l) {
    int idx = blockIdx.x * blockDim.x + threadIdx.x;
    if (idx >= 128 * 64) return;
    int c = idx >> 6, k = idx & 63;
    float v = (c < 64) ? Wpre_l[k * 64 + c] : Wpre_l[(64 + k) * 64 + (c - 64)];
    __nv_bfloat16 h = __float2bfloat16_rn(v);
    __nv_bfloat16 l = __float2bfloat16_rn(v - __bfloat162float(h));
    g_Wth[c * 64 + k] = h;
    g_Wtl[c * 64 + k] = l;
}

__global__ void k_cvtX(const float* __restrict__ X) {
    int gid = blockIdx.x * blockDim.x + threadIdx.x;
    if (gid >= NN * 16) return;
    int r = gid >> 4, q = gid & 15;
    float4 v = *reinterpret_cast<const float4*>(&X[(size_t)r * 64 + q * 4]);
    u32 h0, l0, h1, l1;
    bfsplit2(v.x, v.y, h0, l0);
    bfsplit2(v.z, v.w, h1, l1);
    *reinterpret_cast<u64*>(&g_Ah[(size_t)r * 320 + q * 4]) = (u64)h0 | ((u64)h1 << 32);
    *reinterpret_cast<u64*>(&g_Al[(size_t)r * 320 + q * 4]) = (u64)l0 | ((u64)l1 << 32);
}

// ================= pipelined TC GEMM machinery (256-thread blocks) =================
#define PITCH 40

__device__ __forceinline__ void stageA256(__nv_bfloat16* sAh, __nv_bfloat16* sAl,
                                          int row0, int kc, int tid) {
    int r = tid >> 2, q = tid & 3;          // 64 rows x 4 x 16B
    int n = row0 + r;
    int nc = (n < NN) ? n : (NN - 1);
    int sz = (n < NN) ? 16 : 0;
    cpa16(s2u(sAh + r * PITCH + q * 8), &g_Ah[(size_t)nc * 320 + kc + q * 8], sz);
    cpa16(s2u(sAl + r * PITCH + q * 8), &g_Al[(size_t)nc * 320 + kc + q * 8], sz);
}
__device__ __forceinline__ void stageB192_256(__nv_bfloat16* sBh, __nv_bfloat16* sBl,
                                              int kc, int tid) {
#pragma unroll
    for (int it = 0; it < 3; it++) {
        int idx = tid + it * 256;
        int r = idx >> 2, q = idx & 3;
        cpa16(s2u(sBh + r * PITCH + q * 8), &g_Bth[(size_t)r * 320 + kc + q * 8], 16);
        cpa16(s2u(sBl + r * PITCH + q * 8), &g_Btl[(size_t)r * 320 + kc + q * 8], 16);
    }
}
__device__ __forceinline__ void stageB128_256(__nv_bfloat16* sBh, __nv_bfloat16* sBl,
                                              int kc, int tid) {
#pragma unroll
    for (int it = 0; it < 2; it++) {
        int idx = tid + it * 256;
        int r = idx >> 2, q = idx & 3;
        cpa16(s2u(sBh + r * PITCH + q * 8), &g_Wth[r * 64 + kc + q * 8], 16);
        cpa16(s2u(sBl + r * PITCH + q * 8), &g_Wtl[r * 64 + kc + q * 8], 16);
    }
}

template<int NJ>
__device__ __forceinline__ void tcchunkN(const __nv_bfloat16* sAh, const __nv_bfloat16* sAl,
                                         const __nv_bfloat16* sBh, const __nv_bfloat16* sBl,
                                         int m0, int n0l, int g, int t, float acc[][NJ][4]) {
#pragma unroll
    for (int kk = 0; kk < 32; kk += 16) {
        u32 ah[2][4], al[2][4];
#pragma unroll
        for (int mi = 0; mi < 2; mi++) {
            int r = m0 + mi * 16 + g;
            int cA = kk + 2 * t;
            ah[mi][0] = *reinterpret_cast<const u32*>(&sAh[r * PITCH + cA]);
            ah[mi][1] = *reinterpret_cast<const u32*>(&sAh[(r + 8) * PITCH + cA]);
            ah[mi][2] = *reinterpret_cast<const u32*>(&sAh[r * PITCH + cA + 8]);
            ah[mi][3] = *reinterpret_cast<const u32*>(&sAh[(r + 8) * PITCH + cA + 8]);
            al[mi][0] = *reinterpret_cast<const u32*>(&sAl[r * PITCH + cA]);
            al[mi][1] = *reinterpret_cast<const u32*>(&sAl[(r + 8) * PITCH + cA]);
            al[mi][2] = *reinterpret_cast<const u32*>(&sAl[r * PITCH + cA + 8]);
            al[mi][3] = *reinterpret_cast<const u32*>(&sAl[(r + 8) * PITCH + cA + 8]);
        }
#pragma unroll
        for (int j = 0; j < NJ; j++) {
            int nr = n0l + 8 * j + g;
            int cB = kk + 2 * t;
            u32 bh[2], bl[2];
            bh[0] = *reinterpret_cast<const u32*>(&sBh[nr * PITCH + cB]);
            bh[1] = *reinterpret_cast<const u32*>(&sBh[nr * PITCH + cB + 8]);
            bl[0] = *reinterpret_cast<const u32*>(&sBl[nr * PITCH + cB]);
            bl[1] = *reinterpret_cast<const u32*>(&sBl[nr * PITCH + cB + 8]);
#pragma unroll
            for (int mi = 0; mi < 2; mi++) {
                mma16816(acc[mi][j], ah[mi], bh);
                mma16816(acc[mi][j], ah[mi], bl);
                mma16816(acc[mi][j], al[mi], bh);
            }
        }
    }
}

// ---- fused main GEMM + combine: y[N,64] ; grid 782, 256 thr, dyn smem ----
__global__ void __launch_bounds__(256) k_gemm_tc2() {
    extern __shared__ __nv_bfloat16 dsm[];
    __nv_bfloat16* sAh[2] = {dsm, dsm + 64 * PITCH};
    __nv_bfloat16* sAl[2] = {dsm + 2 * 64 * PITCH, dsm + 3 * 64 * PITCH};
    __nv_bfloat16* base = dsm + 4 * 64 * PITCH;
    __nv_bfloat16* sBh[2] = {base, base + 192 * PITCH};
    __nv_bfloat16* sBl[2] = {base + 2 * 192 * PITCH, base + 3 * 192 * PITCH};
    int tid = threadIdx.x;
    int warp = tid >> 5, lane = tid & 31;
    int g = lane >> 2, t = lane & 3;
    int wm = warp >> 2, wn = warp & 3;      // 2 row-groups x 4 col-groups
    int m0 = wm * 32, n0l = wn * 16;
    int row0 = blockIdx.x * 64;
    float acc[3][2][2][4];
#pragma unroll
    for (int cb = 0; cb < 3; cb++)
#pragma unroll
        for (int mi = 0; mi < 2; mi++)
#pragma unroll
            for (int j = 0; j < 2; j++)
#pragma unroll
                for (int q = 0; q < 4; q++) acc[cb][mi][j][q] = 0.f;

    stageA256(sAh[0], sAl[0], row0, 0, tid);
    stageB192_256(sBh[0], sBl[0], 0, tid);
    CP_COMMIT;
    for (int i = 0; i < 10; i++) {
        int s = i & 1;
        if (i + 1 < 10) {
            stageA256(sAh[s ^ 1], sAl[s ^ 1], row0, (i + 1) * 32, tid);
            stageB192_256(sBh[s ^ 1], sBl[s ^ 1], (i + 1) * 32, tid);
            CP_COMMIT;
            CP_WAIT1;
        } else {
            CP_WAIT0;
        }
        __syncthreads();
#pragma unroll
        for (int cb = 0; cb < 3; cb++)
            tcchunkN<2>(sAh[s], sAl[s], sBh[s] + cb * 64 * PITCH, sBl[s] + cb * 64 * PITCH,
                        m0, n0l, g, t, acc[cb]);
        __syncthreads();
    }
#pragma unroll
    for (int mi = 0; mi < 2; mi++) {
        int r0 = row0 + m0 + mi * 16 + g;
        int r1 = r0 + 8;
        float amp0 = (r0 < NN) ? g_amp[r0] : 0.f;
        float att0 = (r0 < NN) ? g_att[r0] : 0.f;
        float amp1 = (r1 < NN) ? g_amp[r1] : 0.f;
        float att1 = (r1 < NN) ? g_att[r1] : 0.f;
#pragma unroll
        for (int j = 0; j < 2; j++) {
            int c = n0l + 8 * j + 2 * t;
            float b0 = g_bias2[c], b1 = g_bias2[c + 1];
            if (r0 < NN) {
                float y0 = acc[0][mi][j][0] + amp0 * acc[1][mi][j][0] + att0 * acc[2][mi][j][0] + b0;
                float y1 = acc[0][mi][j][1] + amp0 * acc[1][mi][j][1] + att0 * acc[2][mi][j][1] + b1;
                *reinterpret_cast<float2*>(&g_y[(size_t)r0 * 64 + c]) = make_float2(y0, y1);
            }
            if (r1 < NN) {
                float y2 = acc[0][mi][j][2] + amp1 * acc[1][mi][j][2] + att1 * acc[2][mi][j][2] + b0;
                float y3 = acc[0][mi][j][3] + amp1 * acc[1][mi][j][3] + att1 * acc[2][mi][j][3] + b1;
                *reinterpret_cast<float2*>(&g_y[(size_t)r1 * 64 + c]) = make_float2(y2, y3);
            }
        }
    }
}
#define GM2_SMEM ((4 * 64 + 4 * 192) * PITCH * 2)   // 81920 bytes

// ---- fused PQ GEMM: [P|Q][N,128] = X @ Wt ; grid 782, 256 thr, dyn smem ----
__global__ void __launch_bounds__(256) k_pq_tc2() {
    extern __shared__ __nv_bfloat16 dsm[];
    __nv_bfloat16* sAh[2] = {dsm, dsm + 64 * PITCH};
    __nv_bfloat16* sAl[2] = {dsm + 2 * 64 * PITCH, dsm + 3 * 64 * PITCH};
    __nv_bfloat16* base = dsm + 4 * 64 * PITCH;
    __nv_bfloat16* sBh[2] = {base, base + 128 * PITCH};
    __nv_bfloat16* sBl[2] = {base + 2 * 128 * PITCH, base + 3 * 128 * PITCH};
    int tid = threadIdx.x;
    int warp = tid >> 5, lane = tid & 31;
    int g = lane >> 2, t = lane & 3;
    int wm = warp >> 2, wn = warp & 3;      // 2 row-groups x 4 col-groups (32 cols each)
    int m0 = wm * 32, n0l = wn * 32;
    int row0 = blockIdx.x * 64;
    float acc[2][4][4];
#pragma unroll
    for (int mi = 0; mi < 2; mi++)
#pragma unroll
        for (int j = 0; j < 4; j++)
#pragma unroll
            for (int q = 0; q < 4; q++) acc[mi][j][q] = 0.f;

    stageA256(sAh[0], sAl[0], row0, 0, tid);
    stageB128_256(sBh[0], sBl[0], 0, tid);
    CP_COMMIT;
#pragma unroll
    for (int i = 0; i < 2; i++) {
        int s = i & 1;
        if (i + 1 < 2) {
            stageA256(sAh[1], sAl[1], row0, 32, tid);
            stageB128_256(sBh[1], sBl[1], 32, tid);
            CP_COMMIT;
            CP_WAIT1;
        } else {
            CP_WAIT0;
        }
        __syncthreads();
        tcchunkN<4>(sAh[s], sAl[s], sBh[s], sBl[s], m0, n0l, g, t, acc);
        __syncthreads();
    }
    float* dst = (wn < 2) ? g_P : g_Q;
    int cbase = n0l & 63;
#pragma unroll
    for (int mi = 0; mi < 2; mi++) {
#pragma unroll
        for (int j = 0; j < 4; j++) {
            int r = row0 + m0 + mi * 16 + g;
            int c = cbase + 8 * j + 2 * t;
            if (r < NN)
                *reinterpret_cast<float2*>(&dst[(size_t)r * 64 + c]) =
                    make_float2(acc[mi][j][0], acc[mi][j][1]);
            if (r + 8 < NN)
                *reinterpret_cast<float2*>(&dst[(size_t)(r + 8) * 64 + c]) =
                    make_float2(acc[mi][j][2], acc[mi][j][3]);
        }
    }
}
#define PQ2_SMEM ((4 * 64 + 4 * 128) * PITCH * 2)   // 61440 bytes

// ---------------- per-node aggregation (R12 depth-1 form) ----------------
__global__ void __launch_bounds__(256) k_agg() {
    int warp = (blockIdx.x * blockDim.x + threadIdx.x) >> 5;
    int lane = threadIdx.x & 31;
    if (warp >= NN) return;
    int n = warp;
    int fp = 2 * lane;
    u64 wc2[16];
#pragma unroll
    for (int k = 0; k < 16; k++) wc2[k] = *reinterpret_cast<const u64*>(&g_Wc[k * 64 + fp]);
    u64 base2 = fadd2(*reinterpret_cast<const u64*>(&g_P[(size_t)n * FF + fp]),
                      *reinterpret_cast<const u64*>(&g_hb[fp]));
    int s = g_rowptr[n], e = g_rowptr[n + 1];
    u64 sum2 = 0ull, sq2 = 0ull;
    float mn0 = 3.4e38f, mn1 = 3.4e38f, mx0 = -3.4e38f, mx1 = -3.4e38f;
    int src_n = 0; u64 q_n = 0ull;
    if (s < e) {
        src_n = g_csr_src[s];
        q_n = *reinterpret_cast<const u64*>(&g_Q[(size_t)src_n * FF + fp]);
    }
    for (int i = s; i < e; i++) {
        u64 qv = q_n;
        if (i + 1 < e) {
            src_n = g_csr_src[i + 1];
            q_n = *reinterpret_cast<const u64*>(&g_Q[(size_t)src_n * FF + fp]);
        }
        const float* ep = &g_eaperm[(size_t)i * EDD];
        float eav[16];
#pragma unroll
        for (int k = 0; k < 16; k += 4) {
            float4 v = *reinterpret_cast<const float4*>(ep + k);
            eav[k] = v.x; eav[k + 1] = v.y; eav[k + 2] = v.z; eav[k + 3] = v.w;
        }
        u64 hA = fadd2(base2, qv);
        u64 p0 = 0ull, p1 = 0ull;
#pragma unroll
        for (int k = 0; k < 8; k++) {
            p0 = ffma2(pk2(eav[2 * k], eav[2 * k]), wc2[2 * k], p0);
            p1 = ffma2(pk2(eav[2 * k + 1], eav[2 * k + 1]), wc2[2 * k + 1], p1);
        }
        u64 h2 = fadd2(hA, fadd2(p0, p1));
        sum2 = fadd2(sum2, h2);
        sq2 = ffma2(h2, h2, sq2);
        float2 h = up2(h2);
        mn0 = fminf(mn0, h.x); mx0 = fmaxf(mx0, h.x);
        mn1 = fminf(mn1, h.y); mx1 = fmaxf(mx1, h.y);
    }
    float deg = (float)(e - s);
    float degc = fmaxf(deg, 1.0f);
    float2 sum = up2(sum2), sq = up2(sq2);
    float mean0 = sum.x / degc, mean1 = sum.y / degc;
    float std0 = sqrtf(fmaxf(sq.x / degc - mean0 * mean0, 0.f) + 1e-5f);
    float std1 = sqrtf(fmaxf(sq.y / degc - mean1 * mean1, 0.f) + 1e-5f);
    if (deg == 0.f) { mn0 = 0.f; mx0 = 0.f; mn1 = 0.f; mx1 = 0.f; }
    __nv_bfloat16* ah = &g_Ah[(size_t)n * 320 + 64 + fp];
    __nv_bfloat16* al = &g_Al[(size_t)n * 320 + 64 + fp];
    u32 hi, lo;
    bfsplit2(mean0, mean1, hi, lo);
    *reinterpret_cast<u32*>(ah + 0)   = hi; *reinterpret_cast<u32*>(al + 0)   = lo;
    bfsplit2(mn0, mn1, hi, lo);
    *reinterpret_cast<u32*>(ah + 64)  = hi; *reinterpret_cast<u32*>(al + 64)  = lo;
    bfsplit2(mx0, mx1, hi, lo);
    *reinterpret_cast<u32*>(ah + 128) = hi; *reinterpret_cast<u32*>(al + 128) = lo;
    bfsplit2(std0, std1, hi, lo);
    *reinterpret_cast<u32*>(ah + 192) = hi; *reinterpret_cast<u32*>(al + 192) = lo;
}

// ---------------- BN stats over y ----------------
__global__ void __launch_bounds__(256) k_bnstat() {
    int f = threadIdx.x & 63;
    int g = threadIdx.x >> 6;
    __shared__ float sred[256];
    float ys = 0.f, yq = 0.f;
    int n0 = blockIdx.x * 256;
    for (int it = 0; it < 64; it++) {
        int n = n0 + it * 4 + g;
        if (n < NN) {
            float y = g_y[(size_t)n * FF + f];
            ys += y;
            yq = fmaf(y, y, yq);
        }
    }
    sred[threadIdx.x] = ys;
    __syncthreads();
    if (threadIdx.x < 64) {
        float s = sred[f] + sred[64 + f] + sred[128 + f] + sred[192 + f];
        atomicAdd(&g_bnsum[f], s);
    }
    __syncthreads();
    sred[threadIdx.x] = yq;
    __syncthreads();
    if (threadIdx.x < 64) {
        float s = sred[f] + sred[64 + f] + sred[128 + f] + sred[192 + f];
        atomicAdd(&g_bnsq[f], s);
    }
}

__global__ void k_bnfin(const float* __restrict__ gamma_l, const float* __restrict__ beta_l) {
    int f = threadIdx.x;
    if (f >= FF) return;
    float mu = g_bnsum[f] / (float)NN;
    float var = g_bnsq[f] / (float)NN - mu * mu;
    float rs = rsqrtf(var + 1e-5f);
    float a = rs * gamma_l[f];
    g_bnA[f] = a;
    g_bnB[f] = beta_l[f] - mu * a;
    g_bnsum[f] = 0.f;
    g_bnsq[f] = 0.f;
}

__global__ void k_bnapply() {
    int gid = blockIdx.x * blockDim.x + threadIdx.x;
    if (gid >= NN * 16) return;
    int r = gid >> 4, q = gid & 15;
    int f0 = q * 4;
    float4 y = *reinterpret_cast<const float4*>(&g_y[(size_t)r * 64 + f0]);
    float v0 = fmaxf(y.x * g_bnA[f0 + 0] + g_bnB[f0 + 0], 0.f);
    float v1 = fmaxf(y.y * g_bnA[f0 + 1] + g_bnB[f0 + 1], 0.f);
    float v2 = fmaxf(y.z * g_bnA[f0 + 2] + g_bnB[f0 + 2], 0.f);
    float v3 = fmaxf(y.w * g_bnA[f0 + 3] + g_bnB[f0 + 3], 0.f);
    u32 h0, l0, h1, l1;
    bfsplit2(v0, v1, h0, l0);
    bfsplit2(v2, v3, h1, l1);
    *reinterpret_cast<u64*>(&g_Ah[(size_t)r * 320 + f0]) = (u64)h0 | ((u64)h1 << 32);
    *reinterpret_cast<u64*>(&g_Al[(size_t)r * 320 + f0]) = (u64)l0 | ((u64)l1 << 32);
}

__global__ void k_bnpool(const int* __restrict__ batch) {
    int gid = blockIdx.x * blockDim.x + threadIdx.x;
    if (gid >= NN * FF) return;
    int n = gid >> 6, f = gid & 63;
    float v = fmaxf(g_y[gid] * g_bnA[f] + g_bnB[f], 0.f);
    int b = batch[n];
    atomicAdd(&g_gsum[b * FF + f], v);
    if (f == 0) atomicAdd(&g_gcnt[b], 1);
}

__global__ void k_head(const float* __restrict__ W1, const float* __restrict__ b1,
                       const float* __restrict__ W2, const float* __restrict__ b2,
                       float* __restrict__ out) {
    int g = threadIdx.x;
    if (g >= GG) return;
    float cnt = fmaxf((float)g_gcnt[g], 1.0f);
    float inv = 1.0f / cnt;
    float gm[64];
#pragma unroll
    for (int k = 0; k < 64; k++) gm[k] = g_gsum[g * FF + k] * inv;
    float o = b2[0];
    for (int j = 0; j < 40; j++) {
        float s = b1[j];
#pragma unroll
        for (int k = 0; k < 64; k++) s = fmaf(gm[k], W1[k * 40 + j], s);
        o = fmaf(fmaxf(s, 0.f), W2[j], o);
    }
    out[g] = o;
}

// ---------------- launch (fork/join streams inside graph capture) ----------------
extern "C" void kernel_launch(void* const* d_in, const int* in_sizes, int n_in,
                              void* d_out, int out_size) {
    const float* x     = (const float*)d_in[0];
    const float* ea    = (const float*)d_in[1];
    const float* We    = (const float*)d_in[2];
    const float* be    = (const float*)d_in[3];
    const float* Wpre  = (const float*)d_in[4];
    const float* bpre  = (const float*)d_in[5];
    const float* Wpost = (const float*)d_in[6];
    const float* bpost = (const float*)d_in[7];
    const float* Wlin  = (const float*)d_in[8];
    const float* blin  = (const float*)d_in[9];
    const float* gamma = (const float*)d_in[10];
    const float* beta  = (const float*)d_in[11];
    const float* W1    = (const float*)d_in[12];
    const float* b1    = (const float*)d_in[13];
    const float* W2    = (const float*)d_in[14];
    const float* b2    = (const float*)d_in[15];
    const int*   ei    = (const int*)d_in[16];
    const int*   batch = (const int*)d_in[17];
    float* out = (float*)d_out;

    static cudaStream_t s1 = nullptr;
    static cudaEvent_t evA = nullptr, evB = nullptr, evC = nullptr, evD = nullptr;
    if (!s1) {
        cudaStreamCreate(&s1);
        cudaEventCreateWithFlags(&evA, cudaEventDisableTiming);
        cudaEventCreateWithFlags(&evB, cudaEventDisableTiming);
        cudaEventCreateWithFlags(&evC, cudaEventDisableTiming);
        cudaEventCreateWithFlags(&evD, cudaEventDisableTiming);
        cudaFuncSetAttribute(k_pq_tc2, cudaFuncAttributeMaxDynamicSharedMemorySize, PQ2_SMEM);
        cudaFuncSetAttribute(k_gemm_tc2, cudaFuncAttributeMaxDynamicSharedMemorySize, GM2_SMEM);
    }

    int gpq = (NN + 63) / 64;

    // fork: side chain B on s1
    cudaEventRecord(evA, 0);
    cudaStreamWaitEvent(s1, evA, 0);

    // chain A (s0): CSR build
    k_init<<<256, 256>>>();
    k_deg<<<(EE + 255) / 256, 256>>>(ei);
    k_scan1<<<SCB, 1024>>>();
    k_scan3<<<SCB, 1024>>>();
    k_scatter<<<(EE + 255) / 256, 256>>>(ei, ea);

    // chain B (s1): node/weight side, layer 0
    k_cvtX<<<(NN * 16 + 255) / 256, 256, 0, s1>>>(x);
    k_cvtW<<<(128 * 64 + 255) / 256, 256, 0, s1>>>(Wpre);
    k_pq_tc2<<<gpq, 256, PQ2_SMEM, s1>>>();
    k_prep<<<1, 256, 0, s1>>>(We, be, Wpre, bpre, Wlin, bpost, blin);
    k_packB<<<(320 * 192 + 255) / 256, 256, 0, s1>>>(Wpost, Wlin);

    // join
    cudaEventRecord(evB, s1);
    cudaStreamWaitEvent(0, evB, 0);

    // ---- layer 0 ----
    k_agg<<<(NN + 7) / 8, 256>>>();
    k_gemm_tc2<<<gpq, 256, GM2_SMEM>>>();

    // fork: layer-1 weight prep on s1 while BN chain runs on s0
    cudaEventRecord(evC, 0);
    cudaStreamWaitEvent(s1, evC, 0);
    k_prep<<<1, 256, 0, s1>>>(We + EDD * FF, be + FF, Wpre + 192 * FF, bpre + FF,
                              Wlin + FF * FF, bpost + FF, blin + FF);
    k_packB<<<(320 * 192 + 255) / 256, 256, 0, s1>>>(Wpost + 832 * FF, Wlin + FF * FF);
    k_cvtW<<<(128 * 64 + 255) / 256, 256, 0, s1>>>(Wpre + 192 * FF);

    k_bnstat<<<(NN + 255) / 256, 256>>>();
    k_bnfin<<<1, 64>>>(gamma, beta);
    k_bnapply<<<(NN * 16 + 255) / 256, 256>>>();

    // join
    cudaEventRecord(evD, s1);
    cudaStreamWaitEvent(0, evD, 0);

    // ---- layer 1 ----
    k_pq_tc2<<<gpq, 256, PQ2_SMEM>>>();
    k_agg<<<(NN + 7) / 8, 256>>>();
    k_gemm_tc2<<<gpq, 256, GM2_SMEM>>>();
    k_bnstat<<<(NN + 255) / 256, 256>>>();
    k_bnfin<<<1, 64>>>(gamma + FF, beta + FF);
    k_bnpool<<<(NN * FF + 255) / 256, 256>>>(batch);

    k_head<<<1, 64>>>(W1, b1, W2, b2, out);
}